// round 6
// baseline (speedup 1.0000x reference)
#include <cuda_runtime.h>
#include <cstdint>

#define NB   32      // batch
#define SS   400     // src len
#define TDD  30      // trg len
#define EE   256     // embed
#define HH   512     // HE == HD == 512
#define G3   1536    // 3*H
#define VV   50000
#define OOVV 50
#define VO   50050

// ---------------- scratch (device globals; no allocations allowed) ----------------
__device__ float g_Xsrc[SS * NB * EE];
__device__ float g_Xtrg[TDD * NB * EE];
__device__ float g_Gf[(size_t)SS * NB * G3];
__device__ float g_Gb[(size_t)SS * NB * G3];
__device__ float g_Gd[(size_t)TDD * NB * G3];
__device__ float g_enc[(size_t)NB * SS * 2 * HH];
__device__ float g_KP[(size_t)NB * SS * HH];
__device__ float g_Hbuf[2 * 2 * NB * HH];      // [parity][dir][n][h]
__device__ float g_Hdec[TDD * NB * HH];
__device__ float g_Q[TDD * NB * HH];
__device__ float g_ATTN[TDD * NB * SS];
__device__ float g_CTX[TDD * NB * 2 * HH];
__device__ float g_CONC[TDD * NB * G3];
__device__ float g_GEN1[TDD * NB * HH];
__device__ float g_LOG[(size_t)TDD * NB * VV];
__device__ float g_pg[TDD * NB];
__device__ float g_inv[TDD * NB];

// ---------------- helpers ----------------
__device__ __forceinline__ float fsigmoid(float x) { return 1.f / (1.f + __expf(-x)); }
__device__ __forceinline__ float ftanh(float x) {
    x = fminf(fmaxf(x, -15.f), 15.f);
    float e2 = __expf(2.f * x);
    return (e2 - 1.f) / (e2 + 1.f);
}

// ---------------- embedding gather: X[(s*32+n)*256 + e] = embed[ids[n*S+s]][e] ----
__global__ void gather_kernel(const int* __restrict__ ids, const float* __restrict__ embed,
                              float* __restrict__ X, int S)
{
    int row = blockIdx.x;                 // s*32 + n
    int s = row >> 5, n = row & 31;
    int id = ids[n * S + s];
    X[(size_t)row * EE + threadIdx.x] = embed[(size_t)id * EE + threadIdx.x];
}

// ---------------- generic tiled fp32 GEMM: C[M,N] = A[M,K] * op(B) + bias ---------
// transB: B is [N,K] (dot over contiguous K), else B is [K,N].
#define BM 64
#define BN 64
#define BK 16
__global__ void gemm_kernel(const float* __restrict__ A, const float* __restrict__ B,
                            const float* __restrict__ bias, float* __restrict__ C,
                            int M, int N, int K, int transB)
{
    __shared__ float As[BK][BM + 4];
    __shared__ float Bs[BK][BN + 4];
    const int bm = blockIdx.x * BM;
    const int bn = blockIdx.y * BN;
    const int tid = threadIdx.x;
    const int tn = tid & 15, tm = tid >> 4;

    float acc[4][4];
#pragma unroll
    for (int i = 0; i < 4; i++)
#pragma unroll
        for (int j = 0; j < 4; j++) acc[i][j] = 0.f;

    for (int k0 = 0; k0 < K; k0 += BK) {
#pragma unroll
        for (int i = 0; i < 4; i++) {
            int flat = i * 256 + tid;
            int m = flat >> 4, k = flat & 15;
            float v = 0.f;
            if (bm + m < M && k0 + k < K) v = A[(size_t)(bm + m) * K + (k0 + k)];
            As[k][m] = v;
        }
        if (transB) {
#pragma unroll
            for (int i = 0; i < 4; i++) {
                int flat = i * 256 + tid;
                int n = flat >> 4, k = flat & 15;
                float v = 0.f;
                if (bn + n < N && k0 + k < K) v = B[(size_t)(bn + n) * K + (k0 + k)];
                Bs[k][n] = v;
            }
        } else {
#pragma unroll
            for (int i = 0; i < 4; i++) {
                int flat = i * 256 + tid;
                int k = flat >> 6, n = flat & 63;
                float v = 0.f;
                if (k0 + k < K && bn + n < N) v = B[(size_t)(k0 + k) * N + (bn + n)];
                Bs[k][n] = v;
            }
        }
        __syncthreads();
#pragma unroll
        for (int k = 0; k < BK; k++) {
            float4 a4 = *reinterpret_cast<const float4*>(&As[k][tm * 4]);
            float4 b4 = *reinterpret_cast<const float4*>(&Bs[k][tn * 4]);
            float av[4] = {a4.x, a4.y, a4.z, a4.w};
            float bv[4] = {b4.x, b4.y, b4.z, b4.w};
#pragma unroll
            for (int i = 0; i < 4; i++)
#pragma unroll
                for (int j = 0; j < 4; j++) acc[i][j] += av[i] * bv[j];
        }
        __syncthreads();
    }
#pragma unroll
    for (int i = 0; i < 4; i++) {
        int m = bm + tm * 4 + i;
        if (m < M) {
#pragma unroll
            for (int j = 0; j < 4; j++) {
                int n = bn + tn * 4 + j;
                if (n < N) {
                    float r = acc[i][j];
                    if (bias) r += bias[n];
                    C[(size_t)m * N + n] = r;
                }
            }
        }
    }
}

// ---------------- fused GRU step: gh = h@Whh^T (+bhh), gates, store ---------------
// grid.x = ndirs*64 (64 u-tiles of 8); 256 threads; warp w handles hidden unit u = utile*8+w.
// Lane = batch index n. h staged in SMEM as hs[k][n] (two K-halves, padded).
__global__ void gru_step_kernel(const float* __restrict__ Hprev, float* __restrict__ Hnext,
                                const float* __restrict__ G0, const float* __restrict__ G1,
                                const float* __restrict__ Whh0, const float* __restrict__ Whh1,
                                const float* __restrict__ bhh0, const float* __restrict__ bhh1,
                                float* __restrict__ st0, float* __restrict__ st1,
                                int storeStrideN)
{
    const int dir = blockIdx.x >> 6;
    const int utile = blockIdx.x & 63;
    const float* G   = dir ? G1 : G0;
    const float* Whh = dir ? Whh1 : Whh0;
    const float* bhh = dir ? bhh1 : bhh0;
    float* st        = dir ? st1 : st0;
    const float* Hp  = Hprev + (size_t)dir * NB * HH;
    float* Hn        = Hnext + (size_t)dir * NB * HH;

    __shared__ float hs[256][33];
    const int tid = threadIdx.x, lane = tid & 31, warp = tid >> 5;
    const int u = utile * 8 + warp;

    const float* wr = Whh + (size_t)u * HH;
    const float* wz = Whh + (size_t)(HH + u) * HH;
    const float* wn = Whh + (size_t)(2 * HH + u) * HH;

    float ar = 0.f, az = 0.f, an = 0.f;
#pragma unroll
    for (int half = 0; half < 2; half++) {
        const int kb0 = half * 256;
        __syncthreads();
        for (int idx = tid; idx < NB * 256; idx += 256) {
            int n = idx >> 8, k = idx & 255;
            hs[k][n] = Hp[n * HH + kb0 + k];
        }
        __syncthreads();
        for (int kk = 0; kk < 256; kk += 32) {
            float wrv = wr[kb0 + kk + lane];
            float wzv = wz[kb0 + kk + lane];
            float wnv = wn[kb0 + kk + lane];
#pragma unroll
            for (int j = 0; j < 32; j++) {
                float hv = hs[kk + j][lane];
                ar += __shfl_sync(0xffffffffu, wrv, j) * hv;
                az += __shfl_sync(0xffffffffu, wzv, j) * hv;
                an += __shfl_sync(0xffffffffu, wnv, j) * hv;
            }
        }
    }
    const int n = lane;
    float gir = G[n * G3 + u];
    float giz = G[n * G3 + HH + u];
    float gin = G[n * G3 + 2 * HH + u];
    float hr = ar + bhh[u], hz = az + bhh[HH + u], hn = an + bhh[2 * HH + u];
    float r = fsigmoid(gir + hr);
    float z = fsigmoid(giz + hz);
    float nn = ftanh(gin + r * hn);
    float hprev = Hp[n * HH + u];
    float hnew = (1.f - z) * nn + z * hprev;
    Hn[n * HH + u] = hnew;
    st[(size_t)n * storeStrideN + u] = hnew;
}

// ---------------- batched attention (one CTA per (t,n) row) -----------------------
__global__ void attention_kernel(const float* __restrict__ Q, const float* __restrict__ KP,
                                 const float* __restrict__ ENC, const float* __restrict__ mask,
                                 const float* __restrict__ vvec, float* __restrict__ ATTN,
                                 float* __restrict__ CTX)
{
    const int row = blockIdx.x;          // t*32 + n
    const int n = row & 31;
    const int tid = threadIdx.x, lane = tid & 31, warp = tid >> 5;
    __shared__ float qs[HH], vs[HH], es[SS], red[256];

    for (int i = tid; i < HH; i += 256) { qs[i] = Q[(size_t)row * HH + i]; vs[i] = vvec[i]; }
    __syncthreads();

    for (int s = warp; s < SS; s += 8) {
        const float* kp = KP + ((size_t)n * SS + s) * HH;
        float part = 0.f;
        for (int d = lane; d < HH; d += 32)
            part += ftanh(kp[d] + qs[d]) * vs[d];
#pragma unroll
        for (int o = 16; o; o >>= 1) part += __shfl_xor_sync(0xffffffffu, part, o);
        if (lane == 0) es[s] = part + (1.f - mask[n * SS + s]) * (-1e10f);
    }
    __syncthreads();

    float m = -1e30f;
    for (int s = tid; s < SS; s += 256) m = fmaxf(m, es[s]);
    red[tid] = m; __syncthreads();
    for (int st = 128; st; st >>= 1) { if (tid < st) red[tid] = fmaxf(red[tid], red[tid + st]); __syncthreads(); }
    float mx = red[0]; __syncthreads();

    float sum = 0.f;
    for (int s = tid; s < SS; s += 256) { float e = __expf(es[s] - mx); es[s] = e; sum += e; }
    red[tid] = sum; __syncthreads();
    for (int st = 128; st; st >>= 1) { if (tid < st) red[tid] += red[tid + st]; __syncthreads(); }
    float inv = 1.f / red[0]; __syncthreads();

    for (int s = tid; s < SS; s += 256) { float a = es[s] * inv; es[s] = a; ATTN[(size_t)row * SS + s] = a; }
    __syncthreads();

    float a0 = 0.f, a1 = 0.f, a2 = 0.f, a3 = 0.f;
    for (int s = 0; s < SS; s++) {
        float a = es[s];
        const float* er = ENC + ((size_t)n * SS + s) * 1024;
        a0 += a * er[tid];
        a1 += a * er[tid + 256];
        a2 += a * er[tid + 512];
        a3 += a * er[tid + 768];
    }
    CTX[(size_t)row * 1024 + tid]       = a0;
    CTX[(size_t)row * 1024 + tid + 256] = a1;
    CTX[(size_t)row * 1024 + tid + 512] = a2;
    CTX[(size_t)row * 1024 + tid + 768] = a3;
}

// ---------------- concat [h, ctx] --------------------------------------------------
__global__ void concat_kernel(const float* __restrict__ H, const float* __restrict__ CTX,
                              float* __restrict__ C)
{
    int row = blockIdx.x;
    for (int i = threadIdx.x; i < G3; i += 256)
        C[(size_t)row * G3 + i] = (i < HH) ? H[(size_t)row * HH + i]
                                           : CTX[(size_t)row * 1024 + (i - HH)];
}

// ---------------- row softmax over V (stores exp, and 1/sum) ----------------------
__global__ void softmax_kernel(float* __restrict__ LOG, float* __restrict__ invs)
{
    const int row = blockIdx.x, tid = threadIdx.x;
    float* p = LOG + (size_t)row * VV;
    __shared__ float red[256];
    float m = -1e30f;
    for (int i = tid; i < VV; i += 256) m = fmaxf(m, p[i]);
    red[tid] = m; __syncthreads();
    for (int st = 128; st; st >>= 1) { if (tid < st) red[tid] = fmaxf(red[tid], red[tid + st]); __syncthreads(); }
    float mx = red[0]; __syncthreads();
    float sum = 0.f;
    for (int i = tid; i < VV; i += 256) { float e = __expf(p[i] - mx); p[i] = e; sum += e; }
    red[tid] = sum; __syncthreads();
    for (int st = 128; st; st >>= 1) { if (tid < st) red[tid] += red[tid + st]; __syncthreads(); }
    if (tid == 0) invs[row] = 1.f / red[0];
}

// ---------------- p_gen = sigmoid([xi, ctx, h] @ Wp + bp) -------------------------
__global__ void pgen_kernel(const float* __restrict__ Xtrg, const float* __restrict__ CTX,
                            const float* __restrict__ H, const float* __restrict__ Wp,
                            const float* __restrict__ bp, float* __restrict__ pg)
{
    const int warp = threadIdx.x >> 5, lane = threadIdx.x & 31;
    const int row = blockIdx.x * 8 + warp;
    float part = 0.f;
    for (int k = lane; k < 1792; k += 32) {
        float xv;
        if (k < 256)       xv = Xtrg[(size_t)row * EE + k];
        else if (k < 1280) xv = CTX[(size_t)row * 1024 + (k - 256)];
        else               xv = H[(size_t)row * HH + (k - 1280)];
        part += xv * Wp[k];
    }
#pragma unroll
    for (int o = 16; o; o >>= 1) part += __shfl_xor_sync(0xffffffffu, part, o);
    if (lane == 0) pg[row] = fsigmoid(part + bp[0]);
}

// ---------------- out = p_gen * gen_ext (OOV region zeroed) -----------------------
__global__ void outfill_kernel(const float* __restrict__ LOG, const float* __restrict__ pg,
                               const float* __restrict__ invs, float* __restrict__ out)
{
    const int row = blockIdx.y;          // t*32 + n
    const int t = row / NB, n = row % NB;
    const int vv = blockIdx.x * 256 + threadIdx.x;
    if (vv >= VO) return;
    float val = 0.f;
    if (vv < VV) val = pg[row] * invs[row] * LOG[(size_t)row * VV + vv];
    out[((size_t)n * TDD + t) * VO + vv] = val;
}

// ---------------- deterministic scatter-add of (1-p)*attn at ptr indices ----------
__global__ void scatter_kernel(const float* __restrict__ ATTN, const float* __restrict__ pg,
                               const int* __restrict__ ptr_idx, float* __restrict__ out)
{
    const int row = blockIdx.x;          // t*32 + n
    const int t = row / NB, n = row % NB;
    __shared__ int   sidx[SS];
    __shared__ float sw[SS];
    const int s = threadIdx.x;
    const float om = 1.f - pg[row];
    if (s < SS) {
        sidx[s] = ptr_idx[n * SS + s];
        sw[s]   = om * ATTN[(size_t)row * SS + s];
    }
    __syncthreads();
    if (s < SS) {
        int my = sidx[s];
        bool first = true;
        for (int s2 = 0; s2 < s; s2++) if (sidx[s2] == my) { first = false; break; }
        if (first) {
            float val = sw[s];
            for (int s2 = s + 1; s2 < SS; s2++) if (sidx[s2] == my) val += sw[s2];
            out[((size_t)n * TDD + t) * VO + my] += val;   // rows exclusive -> no atomics
        }
    }
}

// ---------------- launch --------------------------------------------------------
extern "C" void kernel_launch(void* const* d_in, const int* in_sizes, int n_in,
                              void* d_out, int out_size)
{
    const int*   src_ids  = (const int*)  d_in[0];
    const float* src_mask = (const float*)d_in[1];
    const int*   trg_ids  = (const int*)  d_in[2];
    const int*   ptr_idx  = (const int*)  d_in[3];
    const float* embed    = (const float*)d_in[4];
    const float* Wih_f = (const float*)d_in[5],  *Whh_f = (const float*)d_in[6];
    const float* bih_f = (const float*)d_in[7],  *bhh_f = (const float*)d_in[8];
    const float* Wih_b = (const float*)d_in[9],  *Whh_b = (const float*)d_in[10];
    const float* bih_b = (const float*)d_in[11], *bhh_b = (const float*)d_in[12];
    const float* Wih_d = (const float*)d_in[13], *Whh_d = (const float*)d_in[14];
    const float* bih_d = (const float*)d_in[15], *bhh_d = (const float*)d_in[16];
    const float* Wk    = (const float*)d_in[17], *Wd    = (const float*)d_in[18];
    const float* battn = (const float*)d_in[19], *vvec  = (const float*)d_in[20];
    const float* W1    = (const float*)d_in[21], *b1    = (const float*)d_in[22];
    const float* W2    = (const float*)d_in[23], *b2    = (const float*)d_in[24];
    const float* Wp    = (const float*)d_in[25], *bp    = (const float*)d_in[26];
    float* out = (float*)d_out;

    float *Xsrc, *Xtrg, *Gf, *Gb, *Gd, *enc, *KP, *Hbuf, *Hdec, *Q, *ATTN, *CTX,
          *CONC, *GEN1, *LOG, *pg, *invs;
    cudaGetSymbolAddress((void**)&Xsrc, g_Xsrc);
    cudaGetSymbolAddress((void**)&Xtrg, g_Xtrg);
    cudaGetSymbolAddress((void**)&Gf,   g_Gf);
    cudaGetSymbolAddress((void**)&Gb,   g_Gb);
    cudaGetSymbolAddress((void**)&Gd,   g_Gd);
    cudaGetSymbolAddress((void**)&enc,  g_enc);
    cudaGetSymbolAddress((void**)&KP,   g_KP);
    cudaGetSymbolAddress((void**)&Hbuf, g_Hbuf);
    cudaGetSymbolAddress((void**)&Hdec, g_Hdec);
    cudaGetSymbolAddress((void**)&Q,    g_Q);
    cudaGetSymbolAddress((void**)&ATTN, g_ATTN);
    cudaGetSymbolAddress((void**)&CTX,  g_CTX);
    cudaGetSymbolAddress((void**)&CONC, g_CONC);
    cudaGetSymbolAddress((void**)&GEN1, g_GEN1);
    cudaGetSymbolAddress((void**)&LOG,  g_LOG);
    cudaGetSymbolAddress((void**)&pg,   g_pg);
    cudaGetSymbolAddress((void**)&invs, g_inv);

    // 1) embedding gathers
    gather_kernel<<<SS * NB, 256>>>(src_ids, embed, Xsrc, SS);
    gather_kernel<<<TDD * NB, 256>>>(trg_ids, embed, Xtrg, TDD);

    // 2) hoisted input projections (gi for all steps, both encoder dirs + decoder)
    gemm_kernel<<<dim3(200, 24), 256>>>(Xsrc, Wih_f, bih_f, Gf, SS * NB, G3, EE, 1);
    gemm_kernel<<<dim3(200, 24), 256>>>(Xsrc, Wih_b, bih_b, Gb, SS * NB, G3, EE, 1);
    gemm_kernel<<<dim3(15, 24), 256>>>(Xtrg, Wih_d, bih_d, Gd, TDD * NB, G3, EE, 1);

    // 3) bidirectional encoder recurrence (400 fused steps)
    const size_t HB = (size_t)2 * NB * HH;   // per-parity buffer (2 dirs)
    cudaMemsetAsync(Hbuf, 0, 2 * HB * sizeof(float), 0);
    for (int t = 0; t < SS; t++) {
        int p = t & 1;
        gru_step_kernel<<<128, 256>>>(Hbuf + p * HB, Hbuf + (1 - p) * HB,
            Gf + (size_t)t * NB * G3, Gb + (size_t)(SS - 1 - t) * NB * G3,
            Whh_f, Whh_b, bhh_f, bhh_b,
            enc + (size_t)t * 1024, enc + (size_t)(SS - 1 - t) * 1024 + HH,
            SS * 1024);
    }

    // 4) attention keys
    gemm_kernel<<<dim3(200, 8), 256>>>(enc, Wk, nullptr, KP, NB * SS, HH, 2 * HH, 0);

    // 5) decoder recurrence (30 fused steps), storing all h_t
    cudaMemsetAsync(Hbuf, 0, 2 * HB * sizeof(float), 0);
    for (int t = 0; t < TDD; t++) {
        int p = t & 1;
        gru_step_kernel<<<64, 256>>>(Hbuf + p * HB, Hbuf + (1 - p) * HB,
            Gd + (size_t)t * NB * G3, nullptr,
            Whh_d, nullptr, bhh_d, nullptr,
            Hdec + (size_t)t * NB * HH, nullptr, HH);
    }

    // 6) batched attention queries + attention + context
    gemm_kernel<<<dim3(15, 8), 256>>>(Hdec, Wd, battn, Q, TDD * NB, HH, HH, 0);
    attention_kernel<<<TDD * NB, 256>>>(Q, KP, enc, src_mask, vvec, ATTN, CTX);

    // 7) batched generator head
    concat_kernel<<<TDD * NB, 256>>>(Hdec, CTX, CONC);
    gemm_kernel<<<dim3(15, 8), 256>>>(CONC, W1, b1, GEN1, TDD * NB, HH, G3, 0);
    gemm_kernel<<<dim3(15, 782), 256>>>(GEN1, W2, b2, LOG, TDD * NB, VV, HH, 0);
    softmax_kernel<<<TDD * NB, 256>>>(LOG, invs);

    // 8) pointer mixture + output assembly
    pgen_kernel<<<(TDD * NB) / 8, 256>>>(Xtrg, CTX, Hdec, Wp, bp, pg);
    outfill_kernel<<<dim3(196, TDD * NB), 256>>>(LOG, pg, invs, out);
    scatter_kernel<<<TDD * NB, 416>>>(ATTN, pg, ptr_idx, out);
}

// round 8
// speedup vs baseline: 1.4519x; 1.4519x over previous
#include <cuda_runtime.h>
#include <cstdint>

#define NB   32      // batch
#define SS   400     // src len
#define TDD  30      // trg len
#define EE   256     // embed
#define HH   512     // HE == HD == 512
#define G3   1536    // 3*H
#define VV   50000
#define OOVV 50
#define VO   50050

#define CDIV(a,b) (((a)+(b)-1)/(b))

// ---------------- scratch (device globals; no allocations allowed) ----------------
__device__ float g_Xsrc[SS * NB * EE];
__device__ float g_Xtrg[TDD * NB * EE];
__device__ float g_Gf[(size_t)SS * NB * G3];    // transposed: [s][col 1536][n 32]
__device__ float g_Gb[(size_t)SS * NB * G3];
__device__ float g_Gd[(size_t)TDD * NB * G3];
__device__ float g_enc[(size_t)NB * SS * 2 * HH];
__device__ float g_KP[(size_t)NB * SS * HH];
__device__ float g_Ht[2 * 2 * HH * NB];         // [parity][dir][k=512][n=32]
__device__ float g_Hdec[TDD * NB * HH];
__device__ float g_Q[TDD * NB * HH];
__device__ float g_ATTN[TDD * NB * SS];
__device__ float g_CTX[TDD * NB * 2 * HH];
__device__ float g_CONC[TDD * NB * G3];
__device__ float g_GEN1[TDD * NB * HH];
__device__ float g_LOG[(size_t)TDD * NB * VV];
__device__ float g_pg[TDD * NB];
__device__ float g_inv[TDD * NB];
__device__ int   g_ctr[576];                    // [0..399] encoder, [512..] decoder

// ---------------- helpers ----------------
__device__ __forceinline__ float fsigmoid(float x) { return 1.f / (1.f + __expf(-x)); }
__device__ __forceinline__ float ftanh(float x) {           // exact-ish (GRU recurrence)
    x = fminf(fmaxf(x, -15.f), 15.f);
    float e2 = __expf(2.f * x);
    return (e2 - 1.f) / (e2 + 1.f);
}
__device__ __forceinline__ float htanh(float x) {           // HW MUFU tanh (attention only)
    float y;
    asm("tanh.approx.f32 %0, %1;" : "=f"(y) : "f"(x));
    return y;
}

// ---------------- embedding gather ------------------------------------------------
__global__ void gather_kernel(const int* __restrict__ ids, const float* __restrict__ embed,
                              float* __restrict__ X, int S)
{
    int row = blockIdx.x;                 // s*32 + n
    int s = row >> 5, n = row & 31;
    int id = ids[n * S + s];
    X[(size_t)row * EE + threadIdx.x] = embed[(size_t)id * EE + threadIdx.x];
}

// ---------------- 128x128x8 fp32 GEMM, 8x8 microtile ------------------------------
// C[M,N] = A[M,K] * op(B) + bias.  transB: B is [N,K] else [K,N].
// gmode: store transposed-per-32-row-group: C[((m>>5)*N + n)*32 + (m&31)]
#define TBM 128
#define TBN 128
#define TBK 8
__global__ __launch_bounds__(256) void gemm128(
    const float* __restrict__ A, const float* __restrict__ B,
    const float* __restrict__ bias, float* __restrict__ C,
    int M, int N, int K, int transB, int gmode)
{
    __shared__ float As[TBK][TBM + 4];
    __shared__ float Bs[TBK][TBN + 4];
    const int bm = blockIdx.x * TBM;
    const int bn = blockIdx.y * TBN;
    const int tid = threadIdx.x;
    const int tm = tid >> 4, tn = tid & 15;

    const int arow = tid >> 1;            // 0..127
    const int akq  = (tid & 1) * 4;       // 0 or 4
    const int bkr  = tid >> 5;            // 0..7
    const int bnc  = (tid & 31) * 4;      // 0..124

    float acc[8][8];
#pragma unroll
    for (int i = 0; i < 8; i++)
#pragma unroll
        for (int j = 0; j < 8; j++) acc[i][j] = 0.f;

    for (int k0 = 0; k0 < K; k0 += TBK) {
        float4 av = make_float4(0.f, 0.f, 0.f, 0.f);
        if (bm + arow < M)
            av = *reinterpret_cast<const float4*>(&A[(size_t)(bm + arow) * K + k0 + akq]);
        As[akq + 0][arow] = av.x;
        As[akq + 1][arow] = av.y;
        As[akq + 2][arow] = av.z;
        As[akq + 3][arow] = av.w;
        if (!transB) {
            float4 bv = make_float4(0.f, 0.f, 0.f, 0.f);
            const float* bp = &B[(size_t)(k0 + bkr) * N + bn + bnc];
            if (bn + bnc + 3 < N) bv = *reinterpret_cast<const float4*>(bp);
            else {
                if (bn + bnc + 0 < N) bv.x = bp[0];
                if (bn + bnc + 1 < N) bv.y = bp[1];
                if (bn + bnc + 2 < N) bv.z = bp[2];
                if (bn + bnc + 3 < N) bv.w = bp[3];
            }
            *reinterpret_cast<float4*>(&Bs[bkr][bnc]) = bv;
        } else {
            float4 bv = make_float4(0.f, 0.f, 0.f, 0.f);
            if (bn + arow < N)
                bv = *reinterpret_cast<const float4*>(&B[(size_t)(bn + arow) * K + k0 + akq]);
            Bs[akq + 0][arow] = bv.x;
            Bs[akq + 1][arow] = bv.y;
            Bs[akq + 2][arow] = bv.z;
            Bs[akq + 3][arow] = bv.w;
        }
        __syncthreads();
#pragma unroll
        for (int k = 0; k < TBK; k++) {
            float4 a0 = *reinterpret_cast<const float4*>(&As[k][tm * 4]);
            float4 a1 = *reinterpret_cast<const float4*>(&As[k][64 + tm * 4]);
            float4 b0 = *reinterpret_cast<const float4*>(&Bs[k][tn * 4]);
            float4 b1 = *reinterpret_cast<const float4*>(&Bs[k][64 + tn * 4]);
            float ar[8] = {a0.x, a0.y, a0.z, a0.w, a1.x, a1.y, a1.z, a1.w};
            float br[8] = {b0.x, b0.y, b0.z, b0.w, b1.x, b1.y, b1.z, b1.w};
#pragma unroll
            for (int i = 0; i < 8; i++)
#pragma unroll
                for (int j = 0; j < 8; j++) acc[i][j] = fmaf(ar[i], br[j], acc[i][j]);
        }
        __syncthreads();
    }
#pragma unroll
    for (int i = 0; i < 8; i++) {
        int m = bm + ((i < 4) ? (tm * 4 + i) : (64 + tm * 4 + i - 4));
        if (m < M) {
#pragma unroll
            for (int j = 0; j < 8; j++) {
                int n = bn + ((j < 4) ? (tn * 4 + j) : (64 + tn * 4 + j - 4));
                if (n < N) {
                    float r = acc[i][j];
                    if (bias) r += __ldg(&bias[n]);
                    if (gmode) C[((size_t)(m >> 5) * N + n) * 32 + (m & 31)] = r;
                    else       C[(size_t)m * N + n] = r;
                }
            }
        }
    }
}

// ---------------- persistent GRU recurrence ---------------------------------------
// encMode=1: 128 CTAs (dir = bid>>6), nSteps=SS, writes enc[n][s][dir*512+u]
// encMode=0: 64 CTAs (dir=0),        nSteps=TDD, writes Hdec[t][n][u]
// h double-buffered in Ht [parity][dir][k][n] via __ldcg/__stcg (L2-coherent).
// G is pre-transposed: G[srow][col][n].
__global__ __launch_bounds__(256, 1) void gru_persist(
    const float* __restrict__ G0T, const float* __restrict__ G1T,
    const float* __restrict__ Whh0, const float* __restrict__ Whh1,
    const float* __restrict__ bhh0, const float* __restrict__ bhh1,
    float* __restrict__ Ht, int* ctr,
    float* __restrict__ encOut, float* __restrict__ hdecOut,
    int nSteps, int nCTA, int encMode)
{
    extern __shared__ float smem[];
    float* ws = smem;                    // [24][512]  c = g*8+uu
    float* rs = smem + 24 * 512;         // [8][24][32]

    const int dir   = encMode ? (blockIdx.x >> 6) : 0;
    const int utile = blockIdx.x & 63;
    const int u0 = utile * 8;
    const float* Whh = dir ? Whh1 : Whh0;
    const float* bhh = dir ? bhh1 : bhh0;
    const float* GT  = dir ? G1T  : G0T;

    const int tid = threadIdx.x, lane = tid & 31, wk = tid >> 5;

    for (int c = 0; c < 24; c++) {
        int g = c >> 3, uu = c & 7;
        const float* src = Whh + (size_t)(g * 512 + u0 + uu) * 512;
        for (int k = tid; k < 512; k += 256) ws[c * 512 + k] = src[k];
    }
    const float b_r = bhh[u0 + wk];
    const float b_z = bhh[512 + u0 + wk];
    const float b_n = bhh[1024 + u0 + wk];
    __syncthreads();

    const int kbase = wk * 64;
    volatile int* vc = ctr;

    for (int t = 0; t < nSteps; t++) {
        const int p = t & 1;
        const float* Hp = Ht + ((size_t)p * 2 + dir) * HH * NB;
        float*       Hn = Ht + ((size_t)(1 - p) * 2 + dir) * HH * NB;
        const int gidx = dir ? (nSteps - 1 - t) : t;
        const float* Gt = GT + (size_t)gidx * G3 * NB;

        float gir = __ldcg(&Gt[(0 * 512 + u0 + wk) * 32 + lane]);
        float giz = __ldcg(&Gt[(1 * 512 + u0 + wk) * 32 + lane]);
        float gin = __ldcg(&Gt[(2 * 512 + u0 + wk) * 32 + lane]);
        float hprev = __ldcg(&Hp[(u0 + wk) * 32 + lane]);

        float acc[24];
#pragma unroll
        for (int c = 0; c < 24; c++) acc[c] = 0.f;
#pragma unroll 2
        for (int k4 = 0; k4 < 16; k4++) {
            const int kb = kbase + k4 * 4;
            float h0 = __ldcg(&Hp[(kb + 0) * 32 + lane]);
            float h1 = __ldcg(&Hp[(kb + 1) * 32 + lane]);
            float h2 = __ldcg(&Hp[(kb + 2) * 32 + lane]);
            float h3 = __ldcg(&Hp[(kb + 3) * 32 + lane]);
#pragma unroll
            for (int c = 0; c < 24; c++) {
                const float4 w = *reinterpret_cast<const float4*>(&ws[c * 512 + kb]);
                acc[c] = fmaf(w.x, h0, fmaf(w.y, h1, fmaf(w.z, h2, fmaf(w.w, h3, acc[c]))));
            }
        }
#pragma unroll
        for (int c = 0; c < 24; c++) rs[(wk * 24 + c) * 32 + lane] = acc[c];
        __syncthreads();

        float ar = 0.f, az = 0.f, an = 0.f;
#pragma unroll
        for (int w2 = 0; w2 < 8; w2++) {
            ar += rs[(w2 * 24 + 0 * 8 + wk) * 32 + lane];
            az += rs[(w2 * 24 + 1 * 8 + wk) * 32 + lane];
            an += rs[(w2 * 24 + 2 * 8 + wk) * 32 + lane];
        }
        float hr = ar + b_r, hz = az + b_z, hn = an + b_n;
        float r = fsigmoid(gir + hr);
        float z = fsigmoid(giz + hz);
        float nn = ftanh(gin + r * hn);
        float hnew = (1.f - z) * nn + z * hprev;
        __stcg(&Hn[(u0 + wk) * 32 + lane], hnew);
        if (encMode) {
            int s = dir ? (nSteps - 1 - t) : t;
            encOut[(size_t)lane * SS * 1024 + (size_t)s * 1024 + dir * 512 + u0 + wk] = hnew;
        } else {
            hdecOut[(size_t)t * NB * HH + (size_t)lane * HH + u0 + wk] = hnew;
        }

        __syncthreads();
        if (tid == 0) {
            __threadfence();
            atomicAdd(&ctr[t], 1);
            while (vc[t] < nCTA) { }
            __threadfence();
        }
        __syncthreads();
    }
}

// ---------------- batched attention (one CTA per (t,n) row) -----------------------
__global__ void attention_kernel(const float* __restrict__ Q, const float* __restrict__ KP,
                                 const float* __restrict__ ENC, const float* __restrict__ mask,
                                 const float* __restrict__ vvec, float* __restrict__ ATTN,
                                 float* __restrict__ CTX)
{
    const int row = blockIdx.x;          // t*32 + n
    const int n = row & 31;
    const int tid = threadIdx.x, lane = tid & 31, warp = tid >> 5;
    __shared__ float qs[HH], vs[HH], es[SS], red[256];

    for (int i = tid; i < HH; i += 256) { qs[i] = Q[(size_t)row * HH + i]; vs[i] = vvec[i]; }
    __syncthreads();

    for (int s = warp; s < SS; s += 8) {
        const float* kp = KP + ((size_t)n * SS + s) * HH;
        float part = 0.f;
        for (int d = lane; d < HH; d += 32)
            part += htanh(kp[d] + qs[d]) * vs[d];
#pragma unroll
        for (int o = 16; o; o >>= 1) part += __shfl_xor_sync(0xffffffffu, part, o);
        if (lane == 0) es[s] = part + (1.f - mask[n * SS + s]) * (-1e10f);
    }
    __syncthreads();

    float m = -1e30f;
    for (int s = tid; s < SS; s += 256) m = fmaxf(m, es[s]);
    red[tid] = m; __syncthreads();
    for (int st = 128; st; st >>= 1) { if (tid < st) red[tid] = fmaxf(red[tid], red[tid + st]); __syncthreads(); }
    float mx = red[0]; __syncthreads();

    float sum = 0.f;
    for (int s = tid; s < SS; s += 256) { float e = __expf(es[s] - mx); es[s] = e; sum += e; }
    red[tid] = sum; __syncthreads();
    for (int st = 128; st; st >>= 1) { if (tid < st) red[tid] += red[tid + st]; __syncthreads(); }
    float inv = 1.f / red[0]; __syncthreads();

    for (int s = tid; s < SS; s += 256) { float a = es[s] * inv; es[s] = a; ATTN[(size_t)row * SS + s] = a; }
    __syncthreads();

    float a0 = 0.f, a1 = 0.f, a2 = 0.f, a3 = 0.f;
    for (int s = 0; s < SS; s++) {
        float a = es[s];
        const float* er = ENC + ((size_t)n * SS + s) * 1024;
        a0 += a * er[tid];
        a1 += a * er[tid + 256];
        a2 += a * er[tid + 512];
        a3 += a * er[tid + 768];
    }
    CTX[(size_t)row * 1024 + tid]       = a0;
    CTX[(size_t)row * 1024 + tid + 256] = a1;
    CTX[(size_t)row * 1024 + tid + 512] = a2;
    CTX[(size_t)row * 1024 + tid + 768] = a3;
}

// ---------------- concat [h, ctx] --------------------------------------------------
__global__ void concat_kernel(const float* __restrict__ H, const float* __restrict__ CTX,
                              float* __restrict__ C)
{
    int row = blockIdx.x;
    for (int i = threadIdx.x; i < G3; i += 256)
        C[(size_t)row * G3 + i] = (i < HH) ? H[(size_t)row * HH + i]
                                           : CTX[(size_t)row * 1024 + (i - HH)];
}

// ---------------- row softmax over V (stores exp, and 1/sum) ----------------------
__global__ void softmax_kernel(float* __restrict__ LOG, float* __restrict__ invs)
{
    const int row = blockIdx.x, tid = threadIdx.x;
    float* p = LOG + (size_t)row * VV;
    __shared__ float red[256];
    float m = -1e30f;
    for (int i = tid; i < VV; i += 256) m = fmaxf(m, p[i]);
    red[tid] = m; __syncthreads();
    for (int st = 128; st; st >>= 1) { if (tid < st) red[tid] = fmaxf(red[tid], red[tid + st]); __syncthreads(); }
    float mx = red[0]; __syncthreads();
    float sum = 0.f;
    for (int i = tid; i < VV; i += 256) { float e = __expf(p[i] - mx); p[i] = e; sum += e; }
    red[tid] = sum; __syncthreads();
    for (int st = 128; st; st >>= 1) { if (tid < st) red[tid] += red[tid + st]; __syncthreads(); }
    if (tid == 0) invs[row] = 1.f / red[0];
}

// ---------------- p_gen = sigmoid([xi, ctx, h] @ Wp + bp) -------------------------
__global__ void pgen_kernel(const float* __restrict__ Xtrg, const float* __restrict__ CTX,
                            const float* __restrict__ H, const float* __restrict__ Wp,
                            const float* __restrict__ bp, float* __restrict__ pg)
{
    const int warp = threadIdx.x >> 5, lane = threadIdx.x & 31;
    const int row = blockIdx.x * 8 + warp;
    float part = 0.f;
    for (int k = lane; k < 1792; k += 32) {
        float xv;
        if (k < 256)       xv = Xtrg[(size_t)row * EE + k];
        else if (k < 1280) xv = CTX[(size_t)row * 1024 + (k - 256)];
        else               xv = H[(size_t)row * HH + (k - 1280)];
        part += xv * Wp[k];
    }
#pragma unroll
    for (int o = 16; o; o >>= 1) part += __shfl_xor_sync(0xffffffffu, part, o);
    if (lane == 0) pg[row] = fsigmoid(part + bp[0]);
}

// ---------------- out = p_gen * gen_ext (OOV region zeroed) -----------------------
__global__ void outfill_kernel(const float* __restrict__ LOG, const float* __restrict__ pg,
                               const float* __restrict__ invs, float* __restrict__ out)
{
    const int row = blockIdx.y;          // t*32 + n
    const int t = row / NB, n = row % NB;
    const int vv = blockIdx.x * 256 + threadIdx.x;
    if (vv >= VO) return;
    float val = 0.f;
    if (vv < VV) val = pg[row] * invs[row] * LOG[(size_t)row * VV + vv];
    out[((size_t)n * TDD + t) * VO + vv] = val;
}

// ---------------- deterministic scatter-add of (1-p)*attn at ptr indices ----------
__global__ void scatter_kernel(const float* __restrict__ ATTN, const float* __restrict__ pg,
                               const int* __restrict__ ptr_idx, float* __restrict__ out)
{
    const int row = blockIdx.x;          // t*32 + n
    const int t = row / NB, n = row % NB;
    __shared__ int   sidx[SS];
    __shared__ float sw[SS];
    const int s = threadIdx.x;
    const float om = 1.f - pg[row];
    if (s < SS) {
        sidx[s] = ptr_idx[n * SS + s];
        sw[s]   = om * ATTN[(size_t)row * SS + s];
    }
    __syncthreads();
    if (s < SS) {
        int my = sidx[s];
        bool first = true;
        for (int s2 = 0; s2 < s; s2++) if (sidx[s2] == my) { first = false; break; }
        if (first) {
            float val = sw[s];
            for (int s2 = s + 1; s2 < SS; s2++) if (sidx[s2] == my) val += sw[s2];
            out[((size_t)n * TDD + t) * VO + my] += val;   // rows exclusive -> no atomics
        }
    }
}

// ---------------- launch --------------------------------------------------------
extern "C" void kernel_launch(void* const* d_in, const int* in_sizes, int n_in,
                              void* d_out, int out_size)
{
    const int*   src_ids  = (const int*)  d_in[0];
    const float* src_mask = (const float*)d_in[1];
    const int*   trg_ids  = (const int*)  d_in[2];
    const int*   ptr_idx  = (const int*)  d_in[3];
    const float* embed    = (const float*)d_in[4];
    const float* Wih_f = (const float*)d_in[5],  *Whh_f = (const float*)d_in[6];
    const float* bih_f = (const float*)d_in[7],  *bhh_f = (const float*)d_in[8];
    const float* Wih_b = (const float*)d_in[9],  *Whh_b = (const float*)d_in[10];
    const float* bih_b = (const float*)d_in[11], *bhh_b = (const float*)d_in[12];
    const float* Wih_d = (const float*)d_in[13], *Whh_d = (const float*)d_in[14];
    const float* bih_d = (const float*)d_in[15], *bhh_d = (const float*)d_in[16];
    const float* Wk    = (const float*)d_in[17], *Wd    = (const float*)d_in[18];
    const float* battn = (const float*)d_in[19], *vvec  = (const float*)d_in[20];
    const float* W1    = (const float*)d_in[21], *b1    = (const float*)d_in[22];
    const float* W2    = (const float*)d_in[23], *b2    = (const float*)d_in[24];
    const float* Wp    = (const float*)d_in[25], *bp    = (const float*)d_in[26];
    float* out = (float*)d_out;

    float *Xsrc, *Xtrg, *Gf, *Gb, *Gd, *enc, *KP, *Ht, *Hdec, *Q, *ATTN, *CTX,
          *CONC, *GEN1, *LOG, *pg, *invs;
    int* ctr;
    cudaGetSymbolAddress((void**)&Xsrc, g_Xsrc);
    cudaGetSymbolAddress((void**)&Xtrg, g_Xtrg);
    cudaGetSymbolAddress((void**)&Gf,   g_Gf);
    cudaGetSymbolAddress((void**)&Gb,   g_Gb);
    cudaGetSymbolAddress((void**)&Gd,   g_Gd);
    cudaGetSymbolAddress((void**)&enc,  g_enc);
    cudaGetSymbolAddress((void**)&KP,   g_KP);
    cudaGetSymbolAddress((void**)&Ht,   g_Ht);
    cudaGetSymbolAddress((void**)&Hdec, g_Hdec);
    cudaGetSymbolAddress((void**)&Q,    g_Q);
    cudaGetSymbolAddress((void**)&ATTN, g_ATTN);
    cudaGetSymbolAddress((void**)&CTX,  g_CTX);
    cudaGetSymbolAddress((void**)&CONC, g_CONC);
    cudaGetSymbolAddress((void**)&GEN1, g_GEN1);
    cudaGetSymbolAddress((void**)&LOG,  g_LOG);
    cudaGetSymbolAddress((void**)&pg,   g_pg);
    cudaGetSymbolAddress((void**)&invs, g_inv);
    cudaGetSymbolAddress((void**)&ctr,  g_ctr);

    static int smemSet = 0;
    if (!smemSet) {
        cudaFuncSetAttribute(gru_persist, cudaFuncAttributeMaxDynamicSharedMemorySize,
                             (24 * 512 + 8 * 24 * 32) * sizeof(float));
        smemSet = 1;
    }
    const int persistSmem = (24 * 512 + 8 * 24 * 32) * sizeof(float);

    // 1) embedding gathers
    gather_kernel<<<SS * NB, 256>>>(src_ids, embed, Xsrc, SS);
    gather_kernel<<<TDD * NB, 256>>>(trg_ids, embed, Xtrg, TDD);

    // 2) hoisted input projections (gmode=1: write [s][col][n] layout)
    gemm128<<<dim3(CDIV(SS * NB, TBM),  CDIV(G3, TBN)), 256>>>(Xsrc, Wih_f, bih_f, Gf, SS * NB,  G3, EE, 1, 1);
    gemm128<<<dim3(CDIV(SS * NB, TBM),  CDIV(G3, TBN)), 256>>>(Xsrc, Wih_b, bih_b, Gb, SS * NB,  G3, EE, 1, 1);
    gemm128<<<dim3(CDIV(TDD * NB, TBM), CDIV(G3, TBN)), 256>>>(Xtrg, Wih_d, bih_d, Gd, TDD * NB, G3, EE, 1, 1);

    // 3) bidirectional encoder recurrence: ONE persistent launch
    cudaMemsetAsync(ctr, 0, 576 * sizeof(int), 0);
    cudaMemsetAsync(Ht, 0, 2 * 2 * HH * NB * sizeof(float), 0);
    gru_persist<<<128, 256, persistSmem>>>(Gf, Gb, Whh_f, Whh_b, bhh_f, bhh_b,
                                           Ht, ctr, enc, nullptr, SS, 128, 1);

    // 4) attention keys
    gemm128<<<dim3(CDIV(NB * SS, TBM), CDIV(HH, TBN)), 256>>>(enc, Wk, nullptr, KP, NB * SS, HH, 2 * HH, 0, 0);

    // 5) decoder recurrence: ONE persistent launch
    cudaMemsetAsync(Ht, 0, 2 * 2 * HH * NB * sizeof(float), 0);
    gru_persist<<<64, 256, persistSmem>>>(Gd, Gd, Whh_d, Whh_d, bhh_d, bhh_d,
                                          Ht, ctr + 512, nullptr, Hdec, TDD, 64, 0);

    // 6) batched attention queries + attention + context
    gemm128<<<dim3(CDIV(TDD * NB, TBM), CDIV(HH, TBN)), 256>>>(Hdec, Wd, battn, Q, TDD * NB, HH, HH, 0, 0);
    attention_kernel<<<TDD * NB, 256>>>(Q, KP, enc, src_mask, vvec, ATTN, CTX);

    // 7) batched generator head
    concat_kernel<<<TDD * NB, 256>>>(Hdec, CTX, CONC);
    gemm128<<<dim3(CDIV(TDD * NB, TBM), CDIV(HH, TBN)), 256>>>(CONC, W1, b1, GEN1, TDD * NB, HH, G3, 0, 0);
    gemm128<<<dim3(CDIV(TDD * NB, TBM), CDIV(VV, TBN)), 256>>>(GEN1, W2, b2, LOG, TDD * NB, VV, HH, 0, 0);
    softmax_kernel<<<TDD * NB, 256>>>(LOG, invs);

    // 8) pointer mixture + output assembly
    pgen_kernel<<<(TDD * NB) / 8, 256>>>(Xtrg, CTX, Hdec, Wp, bp, pg);
    outfill_kernel<<<dim3(CDIV(VO, 256), TDD * NB), 256>>>(LOG, pg, invs, out);
    scatter_kernel<<<TDD * NB, 416>>>(ATTN, pg, ptr_idx, out);
}

// round 9
// speedup vs baseline: 2.8752x; 1.9803x over previous
#include <cuda_runtime.h>
#include <cstdint>

#define NB   32      // batch
#define SS   400     // src len
#define TDD  30      // trg len
#define EE   256     // embed
#define HH   512     // HE == HD == 512
#define G3   1536    // 3*H
#define VV   50000
#define OOVV 50
#define VO   50050

#define CDIV(a,b) (((a)+(b)-1)/(b))

// ---------------- scratch (device globals; no allocations allowed) ----------------
__device__ float g_Xsrc[SS * NB * EE];
__device__ float g_Xtrg[TDD * NB * EE];
__device__ float g_Gf[(size_t)SS * NB * G3];    // transposed: [s][col 1536][n 32]
__device__ float g_Gb[(size_t)SS * NB * G3];
__device__ float g_Gd[(size_t)TDD * NB * G3];
__device__ float g_enc[(size_t)NB * SS * 2 * HH];
__device__ float g_KP[(size_t)NB * SS * HH];
__device__ float g_Ht[2 * 2 * HH * NB];         // [parity][dir][k=512][n=32]
__device__ float g_Hdec[TDD * NB * HH];
__device__ float g_Q[TDD * NB * HH];
__device__ float g_ATTN[TDD * NB * SS];
__device__ float g_CTX[TDD * NB * 2 * HH];
__device__ float g_CONC[TDD * NB * G3];
__device__ float g_GEN1[TDD * NB * HH];
__device__ float g_LOG[(size_t)TDD * NB * VV];
__device__ float g_pg[TDD * NB];
__device__ float g_inv[TDD * NB];
__device__ int   g_ctr[576];                    // [0..399] encoder, [512..] decoder

// ---------------- helpers ----------------
__device__ __forceinline__ float fsigmoid(float x) { return 1.f / (1.f + __expf(-x)); }
__device__ __forceinline__ float ftanh(float x) {           // exact-ish (GRU recurrence)
    x = fminf(fmaxf(x, -15.f), 15.f);
    float e2 = __expf(2.f * x);
    return (e2 - 1.f) / (e2 + 1.f);
}
__device__ __forceinline__ float htanh(float x) {           // HW MUFU tanh (attention only)
    float y;
    asm("tanh.approx.f32 %0, %1;" : "=f"(y) : "f"(x));
    return y;
}
__device__ __forceinline__ uint32_t f2tf(float x) {
    uint32_t u;
    asm("cvt.rna.tf32.f32 %0, %1;" : "=r"(u) : "f"(x));
    return u;
}

// ---------------- embedding gather ------------------------------------------------
__global__ void gather_kernel(const int* __restrict__ ids, const float* __restrict__ embed,
                              float* __restrict__ X, int S)
{
    int row = blockIdx.x;                 // s*32 + n
    int s = row >> 5, n = row & 31;
    int id = ids[n * S + s];
    X[(size_t)row * EE + threadIdx.x] = embed[(size_t)id * EE + threadIdx.x];
}

// ---------------- tf32 tensor-core GEMM -------------------------------------------
// C[M,N] = A[M,K] * op(B) + bias.  transB: B is [N,K] else [K,N].  K % 16 == 0.
// BM=64, BN=128, BK=16; 256 threads = 8 warps (warp grid 2m x 4n), warp tile 32x32.
// gmode: store C[((m>>5)*N + n)*32 + (m&31)]
struct TileRegs { float4 a; float4 b0, b1; };

__device__ __forceinline__ void ldTile(const float* __restrict__ A, const float* __restrict__ B,
                                       int M, int N, int K, int transB,
                                       int bm, int bn, int k0, int tid, TileRegs& r)
{
    const int arow = tid >> 2, akq = (tid & 3) * 4;
    r.a = make_float4(0.f, 0.f, 0.f, 0.f);
    if (bm + arow < M)
        r.a = *reinterpret_cast<const float4*>(&A[(size_t)(bm + arow) * K + k0 + akq]);
    r.b0 = make_float4(0.f, 0.f, 0.f, 0.f);
    r.b1 = make_float4(0.f, 0.f, 0.f, 0.f);
    if (!transB) {
        const int bk = tid >> 4, bnc = (tid & 15) * 8;
        const float* bp = &B[(size_t)(k0 + bk) * N + bn + bnc];
        if (bn + bnc + 7 < N) {
            r.b0 = *reinterpret_cast<const float4*>(bp);
            r.b1 = *reinterpret_cast<const float4*>(bp + 4);
        } else {
            float t[8] = {0.f,0.f,0.f,0.f,0.f,0.f,0.f,0.f};
            for (int i = 0; i < 8; i++) if (bn + bnc + i < N) t[i] = bp[i];
            r.b0 = make_float4(t[0], t[1], t[2], t[3]);
            r.b1 = make_float4(t[4], t[5], t[6], t[7]);
        }
    } else {
        const int n = tid & 127, kh = (tid >> 7) * 8;
        if (bn + n < N) {
            const float* bp = &B[(size_t)(bn + n) * K + k0 + kh];
            r.b0 = *reinterpret_cast<const float4*>(bp);
            r.b1 = *reinterpret_cast<const float4*>(bp + 4);
        }
    }
}

__device__ __forceinline__ void stTile(uint32_t (*As)[20], uint32_t (*Bs)[136],
                                       int transB, int tid, const TileRegs& r)
{
    const int arow = tid >> 2, akq = (tid & 3) * 4;
    As[arow][akq + 0] = f2tf(r.a.x);
    As[arow][akq + 1] = f2tf(r.a.y);
    As[arow][akq + 2] = f2tf(r.a.z);
    As[arow][akq + 3] = f2tf(r.a.w);
    if (!transB) {
        const int bk = tid >> 4, bnc = (tid & 15) * 8;
        Bs[bk][bnc + 0] = f2tf(r.b0.x); Bs[bk][bnc + 1] = f2tf(r.b0.y);
        Bs[bk][bnc + 2] = f2tf(r.b0.z); Bs[bk][bnc + 3] = f2tf(r.b0.w);
        Bs[bk][bnc + 4] = f2tf(r.b1.x); Bs[bk][bnc + 5] = f2tf(r.b1.y);
        Bs[bk][bnc + 6] = f2tf(r.b1.z); Bs[bk][bnc + 7] = f2tf(r.b1.w);
    } else {
        const int n = tid & 127, kh = (tid >> 7) * 8;
        Bs[kh + 0][n] = f2tf(r.b0.x); Bs[kh + 1][n] = f2tf(r.b0.y);
        Bs[kh + 2][n] = f2tf(r.b0.z); Bs[kh + 3][n] = f2tf(r.b0.w);
        Bs[kh + 4][n] = f2tf(r.b1.x); Bs[kh + 5][n] = f2tf(r.b1.y);
        Bs[kh + 6][n] = f2tf(r.b1.z); Bs[kh + 7][n] = f2tf(r.b1.w);
    }
}

__global__ __launch_bounds__(256) void gemm_tf32(
    const float* __restrict__ A, const float* __restrict__ B,
    const float* __restrict__ bias, float* __restrict__ C,
    int M, int N, int K, int transB, int gmode)
{
    __shared__ uint32_t As[2][64][20];
    __shared__ uint32_t Bs[2][16][136];
    const int bm = blockIdx.x * 64;
    const int bn = blockIdx.y * 128;
    const int tid = threadIdx.x;
    const int lane = tid & 31;
    const int warp = tid >> 5;
    const int wm = warp & 1, wn = warp >> 1;   // wm 0..1, wn 0..3

    float acc[2][4][4];
#pragma unroll
    for (int mi = 0; mi < 2; mi++)
#pragma unroll
        for (int ni = 0; ni < 4; ni++)
#pragma unroll
            for (int q = 0; q < 4; q++) acc[mi][ni][q] = 0.f;

    const int KT = K >> 4;
    TileRegs tr;
    ldTile(A, B, M, N, K, transB, bm, bn, 0, tid, tr);
    stTile(As[0], Bs[0], transB, tid, tr);
    __syncthreads();

    for (int kt = 0; kt < KT; kt++) {
        const int cur = kt & 1;
        if (kt + 1 < KT)
            ldTile(A, B, M, N, K, transB, bm, bn, (kt + 1) << 4, tid, tr);
#pragma unroll
        for (int ks = 0; ks < 2; ks++) {
            uint32_t af[2][4], bf[4][2];
            const int r0 = wm * 32 + (lane >> 2);
            const int c0 = ks * 8 + (lane & 3);
#pragma unroll
            for (int mi = 0; mi < 2; mi++) {
                const int rr = r0 + mi * 16;
                af[mi][0] = As[cur][rr][c0];
                af[mi][1] = As[cur][rr + 8][c0];
                af[mi][2] = As[cur][rr][c0 + 4];
                af[mi][3] = As[cur][rr + 8][c0 + 4];
            }
#pragma unroll
            for (int ni = 0; ni < 4; ni++) {
                const int nn = wn * 32 + ni * 8 + (lane >> 2);
                bf[ni][0] = Bs[cur][c0][nn];
                bf[ni][1] = Bs[cur][c0 + 4][nn];
            }
#pragma unroll
            for (int mi = 0; mi < 2; mi++)
#pragma unroll
                for (int ni = 0; ni < 4; ni++)
                    asm volatile(
                        "mma.sync.aligned.m16n8k8.row.col.f32.tf32.tf32.f32 "
                        "{%0,%1,%2,%3}, {%4,%5,%6,%7}, {%8,%9}, {%0,%1,%2,%3};"
                        : "+f"(acc[mi][ni][0]), "+f"(acc[mi][ni][1]),
                          "+f"(acc[mi][ni][2]), "+f"(acc[mi][ni][3])
                        : "r"(af[mi][0]), "r"(af[mi][1]), "r"(af[mi][2]), "r"(af[mi][3]),
                          "r"(bf[ni][0]), "r"(bf[ni][1]));
        }
        if (kt + 1 < KT)
            stTile(As[(kt + 1) & 1], Bs[(kt + 1) & 1], transB, tid, tr);
        __syncthreads();
    }

#pragma unroll
    for (int mi = 0; mi < 2; mi++) {
#pragma unroll
        for (int ni = 0; ni < 4; ni++) {
            const int row = bm + wm * 32 + mi * 16 + (lane >> 2);
            const int col = bn + wn * 32 + ni * 8 + (lane & 3) * 2;
#pragma unroll
            for (int h = 0; h < 2; h++) {
                const int m = row + h * 8;
                if (m < M) {
#pragma unroll
                    for (int q = 0; q < 2; q++) {
                        const int n = col + q;
                        if (n < N) {
                            float v = acc[mi][ni][h * 2 + q];
                            if (bias) v += __ldg(&bias[n]);
                            if (gmode) C[((size_t)(m >> 5) * N + n) * 32 + (m & 31)] = v;
                            else       C[(size_t)m * N + n] = v;
                        }
                    }
                }
            }
        }
    }
}

// ---------------- persistent GRU recurrence ---------------------------------------
__global__ __launch_bounds__(256, 1) void gru_persist(
    const float* __restrict__ G0T, const float* __restrict__ G1T,
    const float* __restrict__ Whh0, const float* __restrict__ Whh1,
    const float* __restrict__ bhh0, const float* __restrict__ bhh1,
    float* __restrict__ Ht, int* ctr,
    float* __restrict__ encOut, float* __restrict__ hdecOut,
    int nSteps, int nCTA, int encMode)
{
    extern __shared__ float smem[];
    float* ws = smem;                    // [24][512]  c = g*8+uu
    float* rs = smem + 24 * 512;         // [8][24][32]

    const int dir   = encMode ? (blockIdx.x >> 6) : 0;
    const int utile = blockIdx.x & 63;
    const int u0 = utile * 8;
    const float* Whh = dir ? Whh1 : Whh0;
    const float* bhh = dir ? bhh1 : bhh0;
    const float* GT  = dir ? G1T  : G0T;

    const int tid = threadIdx.x, lane = tid & 31, wk = tid >> 5;

    for (int c = 0; c < 24; c++) {
        int g = c >> 3, uu = c & 7;
        const float* src = Whh + (size_t)(g * 512 + u0 + uu) * 512;
        for (int k = tid; k < 512; k += 256) ws[c * 512 + k] = src[k];
    }
    const float b_r = bhh[u0 + wk];
    const float b_z = bhh[512 + u0 + wk];
    const float b_n = bhh[1024 + u0 + wk];
    __syncthreads();

    const int kbase = wk * 64;
    volatile int* vc = ctr;

    for (int t = 0; t < nSteps; t++) {
        const int p = t & 1;
        const float* Hp = Ht + ((size_t)p * 2 + dir) * HH * NB;
        float*       Hn = Ht + ((size_t)(1 - p) * 2 + dir) * HH * NB;
        const int gidx = dir ? (nSteps - 1 - t) : t;
        const float* Gt = GT + (size_t)gidx * G3 * NB;

        float gir = __ldcg(&Gt[(0 * 512 + u0 + wk) * 32 + lane]);
        float giz = __ldcg(&Gt[(1 * 512 + u0 + wk) * 32 + lane]);
        float gin = __ldcg(&Gt[(2 * 512 + u0 + wk) * 32 + lane]);
        float hprev = __ldcg(&Hp[(u0 + wk) * 32 + lane]);

        float acc[24];
#pragma unroll
        for (int c = 0; c < 24; c++) acc[c] = 0.f;
#pragma unroll 2
        for (int k4 = 0; k4 < 16; k4++) {
            const int kb = kbase + k4 * 4;
            float h0 = __ldcg(&Hp[(kb + 0) * 32 + lane]);
            float h1 = __ldcg(&Hp[(kb + 1) * 32 + lane]);
            float h2 = __ldcg(&Hp[(kb + 2) * 32 + lane]);
            float h3 = __ldcg(&Hp[(kb + 3) * 32 + lane]);
#pragma unroll
            for (int c = 0; c < 24; c++) {
                const float4 w = *reinterpret_cast<const float4*>(&ws[c * 512 + kb]);
                acc[c] = fmaf(w.x, h0, fmaf(w.y, h1, fmaf(w.z, h2, fmaf(w.w, h3, acc[c]))));
            }
        }
#pragma unroll
        for (int c = 0; c < 24; c++) rs[(wk * 24 + c) * 32 + lane] = acc[c];
        __syncthreads();

        float ar = 0.f, az = 0.f, an = 0.f;
#pragma unroll
        for (int w2 = 0; w2 < 8; w2++) {
            ar += rs[(w2 * 24 + 0 * 8 + wk) * 32 + lane];
            az += rs[(w2 * 24 + 1 * 8 + wk) * 32 + lane];
            an += rs[(w2 * 24 + 2 * 8 + wk) * 32 + lane];
        }
        float hr = ar + b_r, hz = az + b_z, hn = an + b_n;
        float r = fsigmoid(gir + hr);
        float z = fsigmoid(giz + hz);
        float nn = ftanh(gin + r * hn);
        float hnew = (1.f - z) * nn + z * hprev;
        __stcg(&Hn[(u0 + wk) * 32 + lane], hnew);
        if (encMode) {
            int s = dir ? (nSteps - 1 - t) : t;
            encOut[(size_t)lane * SS * 1024 + (size_t)s * 1024 + dir * 512 + u0 + wk] = hnew;
        } else {
            hdecOut[(size_t)t * NB * HH + (size_t)lane * HH + u0 + wk] = hnew;
        }

        __syncthreads();
        if (tid == 0) {
            __threadfence();
            atomicAdd(&ctr[t], 1);
            while (vc[t] < nCTA) { }
            __threadfence();
        }
        __syncthreads();
    }
}

// ---------------- batched attention (one CTA per (t,n) row) -----------------------
__global__ void attention_kernel(const float* __restrict__ Q, const float* __restrict__ KP,
                                 const float* __restrict__ ENC, const float* __restrict__ mask,
                                 const float* __restrict__ vvec, float* __restrict__ ATTN,
                                 float* __restrict__ CTX)
{
    const int row = blockIdx.x;          // t*32 + n
    const int n = row & 31;
    const int tid = threadIdx.x, lane = tid & 31, warp = tid >> 5;
    __shared__ float qs[HH], vs[HH], es[SS], red[256];

    for (int i = tid; i < HH; i += 256) { qs[i] = Q[(size_t)row * HH + i]; vs[i] = vvec[i]; }
    __syncthreads();

    for (int s = warp; s < SS; s += 8) {
        const float* kp = KP + ((size_t)n * SS + s) * HH;
        float part = 0.f;
        for (int d = lane; d < HH; d += 32)
            part += htanh(kp[d] + qs[d]) * vs[d];
#pragma unroll
        for (int o = 16; o; o >>= 1) part += __shfl_xor_sync(0xffffffffu, part, o);
        if (lane == 0) es[s] = part + (1.f - mask[n * SS + s]) * (-1e10f);
    }
    __syncthreads();

    float m = -1e30f;
    for (int s = tid; s < SS; s += 256) m = fmaxf(m, es[s]);
    red[tid] = m; __syncthreads();
    for (int st = 128; st; st >>= 1) { if (tid < st) red[tid] = fmaxf(red[tid], red[tid + st]); __syncthreads(); }
    float mx = red[0]; __syncthreads();

    float sum = 0.f;
    for (int s = tid; s < SS; s += 256) { float e = __expf(es[s] - mx); es[s] = e; sum += e; }
    red[tid] = sum; __syncthreads();
    for (int st = 128; st; st >>= 1) { if (tid < st) red[tid] += red[tid + st]; __syncthreads(); }
    float inv = 1.f / red[0]; __syncthreads();

    for (int s = tid; s < SS; s += 256) { float a = es[s] * inv; es[s] = a; ATTN[(size_t)row * SS + s] = a; }
    __syncthreads();

    float a0 = 0.f, a1 = 0.f, a2 = 0.f, a3 = 0.f;
    for (int s = 0; s < SS; s++) {
        float a = es[s];
        const float* er = ENC + ((size_t)n * SS + s) * 1024;
        a0 += a * er[tid];
        a1 += a * er[tid + 256];
        a2 += a * er[tid + 512];
        a3 += a * er[tid + 768];
    }
    CTX[(size_t)row * 1024 + tid]       = a0;
    CTX[(size_t)row * 1024 + tid + 256] = a1;
    CTX[(size_t)row * 1024 + tid + 512] = a2;
    CTX[(size_t)row * 1024 + tid + 768] = a3;
}

// ---------------- concat [h, ctx] --------------------------------------------------
__global__ void concat_kernel(const float* __restrict__ H, const float* __restrict__ CTX,
                              float* __restrict__ C)
{
    int row = blockIdx.x;
    for (int i = threadIdx.x; i < G3; i += 256)
        C[(size_t)row * G3 + i] = (i < HH) ? H[(size_t)row * HH + i]
                                           : CTX[(size_t)row * 1024 + (i - HH)];
}

// ---------------- row softmax over V (stores exp, and 1/sum) ----------------------
__global__ void softmax_kernel(float* __restrict__ LOG, float* __restrict__ invs)
{
    const int row = blockIdx.x, tid = threadIdx.x;
    float* p = LOG + (size_t)row * VV;
    __shared__ float red[256];
    float m = -1e30f;
    for (int i = tid; i < VV; i += 256) m = fmaxf(m, p[i]);
    red[tid] = m; __syncthreads();
    for (int st = 128; st; st >>= 1) { if (tid < st) red[tid] = fmaxf(red[tid], red[tid + st]); __syncthreads(); }
    float mx = red[0]; __syncthreads();
    float sum = 0.f;
    for (int i = tid; i < VV; i += 256) { float e = __expf(p[i] - mx); p[i] = e; sum += e; }
    red[tid] = sum; __syncthreads();
    for (int st = 128; st; st >>= 1) { if (tid < st) red[tid] += red[tid + st]; __syncthreads(); }
    if (tid == 0) invs[row] = 1.f / red[0];
}

// ---------------- p_gen = sigmoid([xi, ctx, h] @ Wp + bp) -------------------------
__global__ void pgen_kernel(const float* __restrict__ Xtrg, const float* __restrict__ CTX,
                            const float* __restrict__ H, const float* __restrict__ Wp,
                            const float* __restrict__ bp, float* __restrict__ pg)
{
    const int warp = threadIdx.x >> 5, lane = threadIdx.x & 31;
    const int row = blockIdx.x * 8 + warp;
    float part = 0.f;
    for (int k = lane; k < 1792; k += 32) {
        float xv;
        if (k < 256)       xv = Xtrg[(size_t)row * EE + k];
        else if (k < 1280) xv = CTX[(size_t)row * 1024 + (k - 256)];
        else               xv = H[(size_t)row * HH + (k - 1280)];
        part += xv * Wp[k];
    }
#pragma unroll
    for (int o = 16; o; o >>= 1) part += __shfl_xor_sync(0xffffffffu, part, o);
    if (lane == 0) pg[row] = fsigmoid(part + bp[0]);
}

// ---------------- out = p_gen * gen_ext (OOV region zeroed) -----------------------
__global__ void outfill_kernel(const float* __restrict__ LOG, const float* __restrict__ pg,
                               const float* __restrict__ invs, float* __restrict__ out)
{
    const int row = blockIdx.y;          // t*32 + n
    const int t = row / NB, n = row % NB;
    const int vv = blockIdx.x * 256 + threadIdx.x;
    if (vv >= VO) return;
    float val = 0.f;
    if (vv < VV) val = pg[row] * invs[row] * LOG[(size_t)row * VV + vv];
    out[((size_t)n * TDD + t) * VO + vv] = val;
}

// ---------------- deterministic scatter-add of (1-p)*attn at ptr indices ----------
__global__ void scatter_kernel(const float* __restrict__ ATTN, const float* __restrict__ pg,
                               const int* __restrict__ ptr_idx, float* __restrict__ out)
{
    const int row = blockIdx.x;          // t*32 + n
    const int t = row / NB, n = row % NB;
    __shared__ int   sidx[SS];
    __shared__ float sw[SS];
    const int s = threadIdx.x;
    const float om = 1.f - pg[row];
    if (s < SS) {
        sidx[s] = ptr_idx[n * SS + s];
        sw[s]   = om * ATTN[(size_t)row * SS + s];
    }
    __syncthreads();
    if (s < SS) {
        int my = sidx[s];
        bool first = true;
        for (int s2 = 0; s2 < s; s2++) if (sidx[s2] == my) { first = false; break; }
        if (first) {
            float val = sw[s];
            for (int s2 = s + 1; s2 < SS; s2++) if (sidx[s2] == my) val += sw[s2];
            out[((size_t)n * TDD + t) * VO + my] += val;   // rows exclusive -> no atomics
        }
    }
}

// ---------------- launch --------------------------------------------------------
extern "C" void kernel_launch(void* const* d_in, const int* in_sizes, int n_in,
                              void* d_out, int out_size)
{
    const int*   src_ids  = (const int*)  d_in[0];
    const float* src_mask = (const float*)d_in[1];
    const int*   trg_ids  = (const int*)  d_in[2];
    const int*   ptr_idx  = (const int*)  d_in[3];
    const float* embed    = (const float*)d_in[4];
    const float* Wih_f = (const float*)d_in[5],  *Whh_f = (const float*)d_in[6];
    const float* bih_f = (const float*)d_in[7],  *bhh_f = (const float*)d_in[8];
    const float* Wih_b = (const float*)d_in[9],  *Whh_b = (const float*)d_in[10];
    const float* bih_b = (const float*)d_in[11], *bhh_b = (const float*)d_in[12];
    const float* Wih_d = (const float*)d_in[13], *Whh_d = (const float*)d_in[14];
    const float* bih_d = (const float*)d_in[15], *bhh_d = (const float*)d_in[16];
    const float* Wk    = (const float*)d_in[17], *Wd    = (const float*)d_in[18];
    const float* battn = (const float*)d_in[19], *vvec  = (const float*)d_in[20];
    const float* W1    = (const float*)d_in[21], *b1    = (const float*)d_in[22];
    const float* W2    = (const float*)d_in[23], *b2    = (const float*)d_in[24];
    const float* Wp    = (const float*)d_in[25], *bp    = (const float*)d_in[26];
    float* out = (float*)d_out;

    float *Xsrc, *Xtrg, *Gf, *Gb, *Gd, *enc, *KP, *Ht, *Hdec, *Q, *ATTN, *CTX,
          *CONC, *GEN1, *LOG, *pg, *invs;
    int* ctr;
    cudaGetSymbolAddress((void**)&Xsrc, g_Xsrc);
    cudaGetSymbolAddress((void**)&Xtrg, g_Xtrg);
    cudaGetSymbolAddress((void**)&Gf,   g_Gf);
    cudaGetSymbolAddress((void**)&Gb,   g_Gb);
    cudaGetSymbolAddress((void**)&Gd,   g_Gd);
    cudaGetSymbolAddress((void**)&enc,  g_enc);
    cudaGetSymbolAddress((void**)&KP,   g_KP);
    cudaGetSymbolAddress((void**)&Ht,   g_Ht);
    cudaGetSymbolAddress((void**)&Hdec, g_Hdec);
    cudaGetSymbolAddress((void**)&Q,    g_Q);
    cudaGetSymbolAddress((void**)&ATTN, g_ATTN);
    cudaGetSymbolAddress((void**)&CTX,  g_CTX);
    cudaGetSymbolAddress((void**)&CONC, g_CONC);
    cudaGetSymbolAddress((void**)&GEN1, g_GEN1);
    cudaGetSymbolAddress((void**)&LOG,  g_LOG);
    cudaGetSymbolAddress((void**)&pg,   g_pg);
    cudaGetSymbolAddress((void**)&invs, g_inv);
    cudaGetSymbolAddress((void**)&ctr,  g_ctr);

    static int smemSet = 0;
    if (!smemSet) {
        cudaFuncSetAttribute(gru_persist, cudaFuncAttributeMaxDynamicSharedMemorySize,
                             (24 * 512 + 8 * 24 * 32) * sizeof(float));
        smemSet = 1;
    }
    const int persistSmem = (24 * 512 + 8 * 24 * 32) * sizeof(float);

    // 1) embedding gathers
    gather_kernel<<<SS * NB, 256>>>(src_ids, embed, Xsrc, SS);
    gather_kernel<<<TDD * NB, 256>>>(trg_ids, embed, Xtrg, TDD);

    // 2) hoisted input projections (gmode=1: write [s][col][n] layout)
    gemm_tf32<<<dim3(CDIV(SS * NB, 64),  CDIV(G3, 128)), 256>>>(Xsrc, Wih_f, bih_f, Gf, SS * NB,  G3, EE, 1, 1);
    gemm_tf32<<<dim3(CDIV(SS * NB, 64),  CDIV(G3, 128)), 256>>>(Xsrc, Wih_b, bih_b, Gb, SS * NB,  G3, EE, 1, 1);
    gemm_tf32<<<dim3(CDIV(TDD * NB, 64), CDIV(G3, 128)), 256>>>(Xtrg, Wih_d, bih_d, Gd, TDD * NB, G3, EE, 1, 1);

    // 3) bidirectional encoder recurrence: ONE persistent launch
    cudaMemsetAsync(ctr, 0, 576 * sizeof(int), 0);
    cudaMemsetAsync(Ht, 0, 2 * 2 * HH * NB * sizeof(float), 0);
    gru_persist<<<128, 256, persistSmem>>>(Gf, Gb, Whh_f, Whh_b, bhh_f, bhh_b,
                                           Ht, ctr, enc, nullptr, SS, 128, 1);

    // 4) attention keys
    gemm_tf32<<<dim3(CDIV(NB * SS, 64), CDIV(HH, 128)), 256>>>(enc, Wk, nullptr, KP, NB * SS, HH, 2 * HH, 0, 0);

    // 5) decoder recurrence: ONE persistent launch
    cudaMemsetAsync(Ht, 0, 2 * 2 * HH * NB * sizeof(float), 0);
    gru_persist<<<64, 256, persistSmem>>>(Gd, Gd, Whh_d, Whh_d, bhh_d, bhh_d,
                                          Ht, ctr + 512, nullptr, Hdec, TDD, 64, 0);

    // 6) batched attention queries + attention + context
    gemm_tf32<<<dim3(CDIV(TDD * NB, 64), CDIV(HH, 128)), 256>>>(Hdec, Wd, battn, Q, TDD * NB, HH, HH, 0, 0);
    attention_kernel<<<TDD * NB, 256>>>(Q, KP, enc, src_mask, vvec, ATTN, CTX);

    // 7) batched generator head
    concat_kernel<<<TDD * NB, 256>>>(Hdec, CTX, CONC);
    gemm_tf32<<<dim3(CDIV(TDD * NB, 64), CDIV(HH, 128)), 256>>>(CONC, W1, b1, GEN1, TDD * NB, HH, G3, 0, 0);
    gemm_tf32<<<dim3(CDIV(TDD * NB, 64), CDIV(VV, 128)), 256>>>(GEN1, W2, b2, LOG, TDD * NB, VV, HH, 0, 0);
    softmax_kernel<<<TDD * NB, 256>>>(LOG, invs);

    // 8) pointer mixture + output assembly
    pgen_kernel<<<(TDD * NB) / 8, 256>>>(Xtrg, CTX, Hdec, Wp, bp, pg);
    outfill_kernel<<<dim3(CDIV(VO, 256), TDD * NB), 256>>>(LOG, pg, invs, out);
    scatter_kernel<<<TDD * NB, 416>>>(ATTN, pg, ptr_idx, out);
}

// round 10
// speedup vs baseline: 3.2921x; 1.1450x over previous
#include <cuda_runtime.h>
#include <cstdint>

#define NB   32      // batch
#define SS   400     // src len
#define TDD  30      // trg len
#define EE   256     // embed
#define HH   512     // HE == HD == 512
#define G3   1536    // 3*H
#define VV   50000
#define OOVV 50
#define VO   50050

#define CDIV(a,b) (((a)+(b)-1)/(b))

// ---------------- scratch (device globals; no allocations allowed) ----------------
__device__ float g_Xsrc[SS * NB * EE];
__device__ float g_Xtrg[TDD * NB * EE];
__device__ float g_Gf[(size_t)SS * NB * G3];    // transposed: [s][col 1536][n 32]
__device__ float g_Gb[(size_t)SS * NB * G3];
__device__ float g_Gd[(size_t)TDD * NB * G3];
__device__ float g_enc[(size_t)NB * SS * 2 * HH];
__device__ float g_KP[(size_t)NB * SS * HH];
__device__ float g_Ht[2 * 2 * HH * NB];         // [parity][dir][k/4][n][4]
__device__ float g_Hdec[TDD * NB * HH];
__device__ float g_Q[TDD * NB * HH];
__device__ float g_ATTN[TDD * NB * SS];
__device__ float g_CTX[TDD * NB * 2 * HH];
__device__ float g_CONC[TDD * NB * G3];
__device__ float g_GEN1[TDD * NB * HH];
__device__ float g_LOG[(size_t)TDD * NB * VV];
__device__ float g_pg[TDD * NB];
__device__ float g_inv[TDD * NB];
__device__ int   g_ctr[576];                    // [0..399] encoder, [512..] decoder

// ---------------- helpers ----------------
__device__ __forceinline__ float fsigmoid(float x) { return 1.f / (1.f + __expf(-x)); }
__device__ __forceinline__ float ftanh(float x) {           // exact-ish (GRU recurrence)
    x = fminf(fmaxf(x, -15.f), 15.f);
    float e2 = __expf(2.f * x);
    return (e2 - 1.f) / (e2 + 1.f);
}
__device__ __forceinline__ float htanh(float x) {           // HW MUFU tanh (attention only)
    float y;
    asm("tanh.approx.f32 %0, %1;" : "=f"(y) : "f"(x));
    return y;
}
__device__ __forceinline__ uint32_t f2tf(float x) {
    uint32_t u;
    asm("cvt.rna.tf32.f32 %0, %1;" : "=r"(u) : "f"(x));
    return u;
}

// ---------------- embedding gather ------------------------------------------------
__global__ void gather_kernel(const int* __restrict__ ids, const float* __restrict__ embed,
                              float* __restrict__ X, int S)
{
    int row = blockIdx.x;                 // s*32 + n
    int s = row >> 5, n = row & 31;
    int id = ids[n * S + s];
    X[(size_t)row * EE + threadIdx.x] = embed[(size_t)id * EE + threadIdx.x];
}

// ---------------- tf32 tensor-core GEMM v2 ----------------------------------------
// C[M,N] = A[M,K] * op(B) + bias.  transB: B is [N,K] else [K,N].  K % 16 == 0.
// BM=128, BN=128, BK=16; 256 threads = 8 warps (2m x 4n), warp tile 64x32.
// gmode: store C[((m>>5)*N + n)*32 + (m&31)]
struct TileRegs { float4 a0, a1; float4 b0, b1; };

__device__ __forceinline__ void ldTile(const float* __restrict__ A, const float* __restrict__ B,
                                       int M, int N, int K, int transB,
                                       int bm, int bn, int k0, int tid, TileRegs& r)
{
    const int arow = tid >> 1, akq = (tid & 1) * 8;
    r.a0 = make_float4(0.f, 0.f, 0.f, 0.f);
    r.a1 = make_float4(0.f, 0.f, 0.f, 0.f);
    if (bm + arow < M) {
        const float* ap = &A[(size_t)(bm + arow) * K + k0 + akq];
        r.a0 = *reinterpret_cast<const float4*>(ap);
        r.a1 = *reinterpret_cast<const float4*>(ap + 4);
    }
    r.b0 = make_float4(0.f, 0.f, 0.f, 0.f);
    r.b1 = make_float4(0.f, 0.f, 0.f, 0.f);
    if (!transB) {
        const int bk = tid >> 4, bnc = (tid & 15) * 8;
        const float* bp = &B[(size_t)(k0 + bk) * N + bn + bnc];
        if (bn + bnc + 7 < N) {
            r.b0 = *reinterpret_cast<const float4*>(bp);
            r.b1 = *reinterpret_cast<const float4*>(bp + 4);
        } else {
            float t[8] = {0.f,0.f,0.f,0.f,0.f,0.f,0.f,0.f};
            for (int i = 0; i < 8; i++) if (bn + bnc + i < N) t[i] = bp[i];
            r.b0 = make_float4(t[0], t[1], t[2], t[3]);
            r.b1 = make_float4(t[4], t[5], t[6], t[7]);
        }
    } else {
        const int n = tid & 127, kh = (tid >> 7) * 8;
        if (bn + n < N) {
            const float* bp = &B[(size_t)(bn + n) * K + k0 + kh];
            r.b0 = *reinterpret_cast<const float4*>(bp);
            r.b1 = *reinterpret_cast<const float4*>(bp + 4);
        }
    }
}

__device__ __forceinline__ void stTile(uint32_t (*As)[20], uint32_t (*Bs)[136],
                                       int transB, int tid, const TileRegs& r)
{
    const int arow = tid >> 1, akq = (tid & 1) * 8;
    As[arow][akq + 0] = f2tf(r.a0.x); As[arow][akq + 1] = f2tf(r.a0.y);
    As[arow][akq + 2] = f2tf(r.a0.z); As[arow][akq + 3] = f2tf(r.a0.w);
    As[arow][akq + 4] = f2tf(r.a1.x); As[arow][akq + 5] = f2tf(r.a1.y);
    As[arow][akq + 6] = f2tf(r.a1.z); As[arow][akq + 7] = f2tf(r.a1.w);
    if (!transB) {
        const int bk = tid >> 4, bnc = (tid & 15) * 8;
        Bs[bk][bnc + 0] = f2tf(r.b0.x); Bs[bk][bnc + 1] = f2tf(r.b0.y);
        Bs[bk][bnc + 2] = f2tf(r.b0.z); Bs[bk][bnc + 3] = f2tf(r.b0.w);
        Bs[bk][bnc + 4] = f2tf(r.b1.x); Bs[bk][bnc + 5] = f2tf(r.b1.y);
        Bs[bk][bnc + 6] = f2tf(r.b1.z); Bs[bk][bnc + 7] = f2tf(r.b1.w);
    } else {
        const int n = tid & 127, kh = (tid >> 7) * 8;
        Bs[kh + 0][n] = f2tf(r.b0.x); Bs[kh + 1][n] = f2tf(r.b0.y);
        Bs[kh + 2][n] = f2tf(r.b0.z); Bs[kh + 3][n] = f2tf(r.b0.w);
        Bs[kh + 4][n] = f2tf(r.b1.x); Bs[kh + 5][n] = f2tf(r.b1.y);
        Bs[kh + 6][n] = f2tf(r.b1.z); Bs[kh + 7][n] = f2tf(r.b1.w);
    }
}

__global__ __launch_bounds__(256) void gemm_tf32(
    const float* __restrict__ A, const float* __restrict__ B,
    const float* __restrict__ bias, float* __restrict__ C,
    int M, int N, int K, int transB, int gmode)
{
    __shared__ uint32_t As[2][128][20];
    __shared__ uint32_t Bs[2][16][136];
    const int bm = blockIdx.x * 128;
    const int bn = blockIdx.y * 128;
    const int tid = threadIdx.x;
    const int lane = tid & 31;
    const int warp = tid >> 5;
    const int wm = warp & 1, wn = warp >> 1;   // warp tile 64m x 32n

    float acc[4][4][4];
#pragma unroll
    for (int mi = 0; mi < 4; mi++)
#pragma unroll
        for (int ni = 0; ni < 4; ni++)
#pragma unroll
            for (int q = 0; q < 4; q++) acc[mi][ni][q] = 0.f;

    const int KT = K >> 4;
    TileRegs tr;
    ldTile(A, B, M, N, K, transB, bm, bn, 0, tid, tr);
    stTile(As[0], Bs[0], transB, tid, tr);
    __syncthreads();

    for (int kt = 0; kt < KT; kt++) {
        const int cur = kt & 1;
        if (kt + 1 < KT)
            ldTile(A, B, M, N, K, transB, bm, bn, (kt + 1) << 4, tid, tr);
#pragma unroll
        for (int ks = 0; ks < 2; ks++) {
            uint32_t af[4][4], bf[4][2];
            const int r0 = wm * 64 + (lane >> 2);
            const int c0 = ks * 8 + (lane & 3);
#pragma unroll
            for (int mi = 0; mi < 4; mi++) {
                const int rr = r0 + mi * 16;
                af[mi][0] = As[cur][rr][c0];
                af[mi][1] = As[cur][rr + 8][c0];
                af[mi][2] = As[cur][rr][c0 + 4];
                af[mi][3] = As[cur][rr + 8][c0 + 4];
            }
#pragma unroll
            for (int ni = 0; ni < 4; ni++) {
                const int nn = wn * 32 + ni * 8 + (lane >> 2);
                bf[ni][0] = Bs[cur][c0][nn];
                bf[ni][1] = Bs[cur][c0 + 4][nn];
            }
#pragma unroll
            for (int mi = 0; mi < 4; mi++)
#pragma unroll
                for (int ni = 0; ni < 4; ni++)
                    asm volatile(
                        "mma.sync.aligned.m16n8k8.row.col.f32.tf32.tf32.f32 "
                        "{%0,%1,%2,%3}, {%4,%5,%6,%7}, {%8,%9}, {%0,%1,%2,%3};"
                        : "+f"(acc[mi][ni][0]), "+f"(acc[mi][ni][1]),
                          "+f"(acc[mi][ni][2]), "+f"(acc[mi][ni][3])
                        : "r"(af[mi][0]), "r"(af[mi][1]), "r"(af[mi][2]), "r"(af[mi][3]),
                          "r"(bf[ni][0]), "r"(bf[ni][1]));
        }
        if (kt + 1 < KT)
            stTile(As[(kt + 1) & 1], Bs[(kt + 1) & 1], transB, tid, tr);
        __syncthreads();
    }

#pragma unroll
    for (int mi = 0; mi < 4; mi++) {
#pragma unroll
        for (int ni = 0; ni < 4; ni++) {
            const int row = bm + wm * 64 + mi * 16 + (lane >> 2);
            const int col = bn + wn * 32 + ni * 8 + (lane & 3) * 2;
#pragma unroll
            for (int h = 0; h < 2; h++) {
                const int m = row + h * 8;
                if (m < M) {
#pragma unroll
                    for (int q = 0; q < 2; q++) {
                        const int n = col + q;
                        if (n < N) {
                            float v = acc[mi][ni][h * 2 + q];
                            if (bias) v += __ldg(&bias[n]);
                            if (gmode) C[((size_t)(m >> 5) * N + n) * 32 + (m & 31)] = v;
                            else       C[(size_t)m * N + n] = v;
                        }
                    }
                }
            }
        }
    }
}

// ---------------- persistent GRU recurrence (512 threads) -------------------------
// h stored packed [parity][dir][k/4][n][4] -> one LDG.128 per (k4,n).
// 16 warps: each owns k-slice of 32 (8 float4 groups). Warps 0..7 also own unit u0+wk
// for the gate phase and carry hprev in a register.
__global__ __launch_bounds__(512, 1) void gru_persist(
    const float* __restrict__ G0T, const float* __restrict__ G1T,
    const float* __restrict__ Whh0, const float* __restrict__ Whh1,
    const float* __restrict__ bhh0, const float* __restrict__ bhh1,
    float* __restrict__ Ht, int* ctr,
    float* __restrict__ encOut, float* __restrict__ hdecOut,
    int nSteps, int nCTA, int encMode)
{
    extern __shared__ float smem[];
    float* ws = smem;                    // [24][512]  c = g*8+uu
    float* rs = smem + 24 * 512;         // [16][24][32]

    const int dir   = encMode ? (blockIdx.x >> 6) : 0;
    const int utile = blockIdx.x & 63;
    const int u0 = utile * 8;
    const float* Whh = dir ? Whh1 : Whh0;
    const float* bhh = dir ? bhh1 : bhh0;
    const float* GT  = dir ? G1T  : G0T;

    const int tid = threadIdx.x, lane = tid & 31, wk = tid >> 5;   // wk 0..15

    for (int c = 0; c < 24; c++) {
        int g = c >> 3, uu = c & 7;
        const float* src = Whh + (size_t)(g * 512 + u0 + uu) * 512;
        for (int k = tid; k < 512; k += 512) ws[c * 512 + k] = src[k];
    }
    float b_r = 0.f, b_z = 0.f, b_n = 0.f;
    const int u = u0 + wk;               // valid for wk < 8
    if (wk < 8) {
        b_r = bhh[u];
        b_z = bhh[512 + u];
        b_n = bhh[1024 + u];
    }
    __syncthreads();

    const int kb4 = wk * 8;              // this warp's 8 float4 k-groups
    float hprev = 0.f;                   // register-carried own h

    for (int t = 0; t < nSteps; t++) {
        const int p = t & 1;
        const float4* Hp4 = reinterpret_cast<const float4*>(Ht + ((size_t)p * 2 + dir) * HH * NB);
        float*        Hnf = Ht + ((size_t)(1 - p) * 2 + dir) * HH * NB;
        const int gidx = dir ? (nSteps - 1 - t) : t;
        const float* Gt = GT + (size_t)gidx * G3 * NB;

        float gir = 0.f, giz = 0.f, gin = 0.f;
        if (wk < 8) {
            gir = __ldg(&Gt[u * 32 + lane]);
            giz = __ldg(&Gt[(512 + u) * 32 + lane]);
            gin = __ldg(&Gt[(1024 + u) * 32 + lane]);
        }

        float acc[24];
#pragma unroll
        for (int c = 0; c < 24; c++) acc[c] = 0.f;
#pragma unroll
        for (int k4 = 0; k4 < 8; k4++) {
            float4 h4 = __ldcg(&Hp4[(size_t)(kb4 + k4) * 32 + lane]);
            const int kb = (kb4 + k4) * 4;
#pragma unroll
            for (int c = 0; c < 24; c++) {
                const float4 w = *reinterpret_cast<const float4*>(&ws[c * 512 + kb]);
                acc[c] = fmaf(w.x, h4.x, fmaf(w.y, h4.y, fmaf(w.z, h4.z, fmaf(w.w, h4.w, acc[c]))));
            }
        }
#pragma unroll
        for (int c = 0; c < 24; c++) rs[(wk * 24 + c) * 32 + lane] = acc[c];
        __syncthreads();

        if (wk < 8) {
            float ar = 0.f, az = 0.f, an = 0.f;
#pragma unroll
            for (int w2 = 0; w2 < 16; w2++) {
                ar += rs[(w2 * 24 + 0 * 8 + wk) * 32 + lane];
                az += rs[(w2 * 24 + 1 * 8 + wk) * 32 + lane];
                an += rs[(w2 * 24 + 2 * 8 + wk) * 32 + lane];
            }
            float r = fsigmoid(gir + ar + b_r);
            float z = fsigmoid(giz + az + b_z);
            float nn = ftanh(gin + (an + b_n) * r);
            float hnew = (1.f - z) * nn + z * hprev;
            hprev = hnew;
            __stcg(&Hnf[(u >> 2) * 128 + lane * 4 + (u & 3)], hnew);
            if (encMode) {
                int s = dir ? (nSteps - 1 - t) : t;
                encOut[(size_t)lane * SS * 1024 + (size_t)s * 1024 + dir * 512 + u] = hnew;
            } else {
                hdecOut[(size_t)t * NB * HH + (size_t)lane * HH + u] = hnew;
            }
        }
        __syncthreads();

        if (t + 1 < nSteps) {
            if (tid == 0) {
                int* a = &ctr[t];
                asm volatile("red.release.gpu.global.add.u32 [%0], 1;" :: "l"(a) : "memory");
                unsigned v;
                do {
                    asm volatile("ld.acquire.gpu.global.u32 %0, [%1];" : "=r"(v) : "l"(a) : "memory");
                } while (v < (unsigned)nCTA);
            }
            __syncthreads();
        }
    }
}

// ---------------- batched attention (one CTA per (t,n) row) -----------------------
__global__ void attention_kernel(const float* __restrict__ Q, const float* __restrict__ KP,
                                 const float* __restrict__ ENC, const float* __restrict__ mask,
                                 const float* __restrict__ vvec, float* __restrict__ ATTN,
                                 float* __restrict__ CTX)
{
    const int row = blockIdx.x;          // t*32 + n
    const int n = row & 31;
    const int tid = threadIdx.x, lane = tid & 31, warp = tid >> 5;
    __shared__ float qs[HH], vs[HH], es[SS], red[256];

    for (int i = tid; i < HH; i += 256) { qs[i] = Q[(size_t)row * HH + i]; vs[i] = vvec[i]; }
    __syncthreads();

    for (int s = warp; s < SS; s += 8) {
        const float* kp = KP + ((size_t)n * SS + s) * HH;
        float part = 0.f;
        for (int d = lane; d < HH; d += 32)
            part += htanh(kp[d] + qs[d]) * vs[d];
#pragma unroll
        for (int o = 16; o; o >>= 1) part += __shfl_xor_sync(0xffffffffu, part, o);
        if (lane == 0) es[s] = part + (1.f - mask[n * SS + s]) * (-1e10f);
    }
    __syncthreads();

    float m = -1e30f;
    for (int s = tid; s < SS; s += 256) m = fmaxf(m, es[s]);
    red[tid] = m; __syncthreads();
    for (int st = 128; st; st >>= 1) { if (tid < st) red[tid] = fmaxf(red[tid], red[tid + st]); __syncthreads(); }
    float mx = red[0]; __syncthreads();

    float sum = 0.f;
    for (int s = tid; s < SS; s += 256) { float e = __expf(es[s] - mx); es[s] = e; sum += e; }
    red[tid] = sum; __syncthreads();
    for (int st = 128; st; st >>= 1) { if (tid < st) red[tid] += red[tid + st]; __syncthreads(); }
    float inv = 1.f / red[0]; __syncthreads();

    for (int s = tid; s < SS; s += 256) { float a = es[s] * inv; es[s] = a; ATTN[(size_t)row * SS + s] = a; }
    __syncthreads();

    float a0 = 0.f, a1 = 0.f, a2 = 0.f, a3 = 0.f;
    for (int s = 0; s < SS; s++) {
        float a = es[s];
        const float* er = ENC + ((size_t)n * SS + s) * 1024;
        a0 += a * er[tid];
        a1 += a * er[tid + 256];
        a2 += a * er[tid + 512];
        a3 += a * er[tid + 768];
    }
    CTX[(size_t)row * 1024 + tid]       = a0;
    CTX[(size_t)row * 1024 + tid + 256] = a1;
    CTX[(size_t)row * 1024 + tid + 512] = a2;
    CTX[(size_t)row * 1024 + tid + 768] = a3;
}

// ---------------- concat [h, ctx] --------------------------------------------------
__global__ void concat_kernel(const float* __restrict__ H, const float* __restrict__ CTX,
                              float* __restrict__ C)
{
    int row = blockIdx.x;
    for (int i = threadIdx.x; i < G3; i += 256)
        C[(size_t)row * G3 + i] = (i < HH) ? H[(size_t)row * HH + i]
                                           : CTX[(size_t)row * 1024 + (i - HH)];
}

// ---------------- row softmax over V (stores exp, and 1/sum) ----------------------
__global__ void softmax_kernel(float* __restrict__ LOG, float* __restrict__ invs)
{
    const int row = blockIdx.x, tid = threadIdx.x;
    float* p = LOG + (size_t)row * VV;
    __shared__ float red[256];
    float m = -1e30f;
    for (int i = tid; i < VV; i += 256) m = fmaxf(m, p[i]);
    red[tid] = m; __syncthreads();
    for (int st = 128; st; st >>= 1) { if (tid < st) red[tid] = fmaxf(red[tid], red[tid + st]); __syncthreads(); }
    float mx = red[0]; __syncthreads();
    float sum = 0.f;
    for (int i = tid; i < VV; i += 256) { float e = __expf(p[i] - mx); p[i] = e; sum += e; }
    red[tid] = sum; __syncthreads();
    for (int st = 128; st; st >>= 1) { if (tid < st) red[tid] += red[tid + st]; __syncthreads(); }
    if (tid == 0) invs[row] = 1.f / red[0];
}

// ---------------- p_gen = sigmoid([xi, ctx, h] @ Wp + bp) -------------------------
__global__ void pgen_kernel(const float* __restrict__ Xtrg, const float* __restrict__ CTX,
                            const float* __restrict__ H, const float* __restrict__ Wp,
                            const float* __restrict__ bp, float* __restrict__ pg)
{
    const int warp = threadIdx.x >> 5, lane = threadIdx.x & 31;
    const int row = blockIdx.x * 8 + warp;
    float part = 0.f;
    for (int k = lane; k < 1792; k += 32) {
        float xv;
        if (k < 256)       xv = Xtrg[(size_t)row * EE + k];
        else if (k < 1280) xv = CTX[(size_t)row * 1024 + (k - 256)];
        else               xv = H[(size_t)row * HH + (k - 1280)];
        part += xv * Wp[k];
    }
#pragma unroll
    for (int o = 16; o; o >>= 1) part += __shfl_xor_sync(0xffffffffu, part, o);
    if (lane == 0) pg[row] = fsigmoid(part + bp[0]);
}

// ---------------- out = p_gen * gen_ext (OOV region zeroed) -----------------------
__global__ void outfill_kernel(const float* __restrict__ LOG, const float* __restrict__ pg,
                               const float* __restrict__ invs, float* __restrict__ out)
{
    const int row = blockIdx.y;          // t*32 + n
    const int t = row / NB, n = row % NB;
    const int vv = blockIdx.x * 256 + threadIdx.x;
    if (vv >= VO) return;
    float val = 0.f;
    if (vv < VV) val = pg[row] * invs[row] * LOG[(size_t)row * VV + vv];
    out[((size_t)n * TDD + t) * VO + vv] = val;
}

// ---------------- deterministic scatter-add of (1-p)*attn at ptr indices ----------
__global__ void scatter_kernel(const float* __restrict__ ATTN, const float* __restrict__ pg,
                               const int* __restrict__ ptr_idx, float* __restrict__ out)
{
    const int row = blockIdx.x;          // t*32 + n
    const int t = row / NB, n = row % NB;
    __shared__ int   sidx[SS];
    __shared__ float sw[SS];
    const int s = threadIdx.x;
    const float om = 1.f - pg[row];
    if (s < SS) {
        sidx[s] = ptr_idx[n * SS + s];
        sw[s]   = om * ATTN[(size_t)row * SS + s];
    }
    __syncthreads();
    if (s < SS) {
        int my = sidx[s];
        bool first = true;
        for (int s2 = 0; s2 < s; s2++) if (sidx[s2] == my) { first = false; break; }
        if (first) {
            float val = sw[s];
            for (int s2 = s + 1; s2 < SS; s2++) if (sidx[s2] == my) val += sw[s2];
            out[((size_t)n * TDD + t) * VO + my] += val;   // rows exclusive -> no atomics
        }
    }
}

// ---------------- launch --------------------------------------------------------
extern "C" void kernel_launch(void* const* d_in, const int* in_sizes, int n_in,
                              void* d_out, int out_size)
{
    const int*   src_ids  = (const int*)  d_in[0];
    const float* src_mask = (const float*)d_in[1];
    const int*   trg_ids  = (const int*)  d_in[2];
    const int*   ptr_idx  = (const int*)  d_in[3];
    const float* embed    = (const float*)d_in[4];
    const float* Wih_f = (const float*)d_in[5],  *Whh_f = (const float*)d_in[6];
    const float* bih_f = (const float*)d_in[7],  *bhh_f = (const float*)d_in[8];
    const float* Wih_b = (const float*)d_in[9],  *Whh_b = (const float*)d_in[10];
    const float* bih_b = (const float*)d_in[11], *bhh_b = (const float*)d_in[12];
    const float* Wih_d = (const float*)d_in[13], *Whh_d = (const float*)d_in[14];
    const float* bih_d = (const float*)d_in[15], *bhh_d = (const float*)d_in[16];
    const float* Wk    = (const float*)d_in[17], *Wd    = (const float*)d_in[18];
    const float* battn = (const float*)d_in[19], *vvec  = (const float*)d_in[20];
    const float* W1    = (const float*)d_in[21], *b1    = (const float*)d_in[22];
    const float* W2    = (const float*)d_in[23], *b2    = (const float*)d_in[24];
    const float* Wp    = (const float*)d_in[25], *bp    = (const float*)d_in[26];
    float* out = (float*)d_out;

    float *Xsrc, *Xtrg, *Gf, *Gb, *Gd, *enc, *KP, *Ht, *Hdec, *Q, *ATTN, *CTX,
          *CONC, *GEN1, *LOG, *pg, *invs;
    int* ctr;
    cudaGetSymbolAddress((void**)&Xsrc, g_Xsrc);
    cudaGetSymbolAddress((void**)&Xtrg, g_Xtrg);
    cudaGetSymbolAddress((void**)&Gf,   g_Gf);
    cudaGetSymbolAddress((void**)&Gb,   g_Gb);
    cudaGetSymbolAddress((void**)&Gd,   g_Gd);
    cudaGetSymbolAddress((void**)&enc,  g_enc);
    cudaGetSymbolAddress((void**)&KP,   g_KP);
    cudaGetSymbolAddress((void**)&Ht,   g_Ht);
    cudaGetSymbolAddress((void**)&Hdec, g_Hdec);
    cudaGetSymbolAddress((void**)&Q,    g_Q);
    cudaGetSymbolAddress((void**)&ATTN, g_ATTN);
    cudaGetSymbolAddress((void**)&CTX,  g_CTX);
    cudaGetSymbolAddress((void**)&CONC, g_CONC);
    cudaGetSymbolAddress((void**)&GEN1, g_GEN1);
    cudaGetSymbolAddress((void**)&LOG,  g_LOG);
    cudaGetSymbolAddress((void**)&pg,   g_pg);
    cudaGetSymbolAddress((void**)&invs, g_inv);
    cudaGetSymbolAddress((void**)&ctr,  g_ctr);

    const int persistSmem = (24 * 512 + 16 * 24 * 32) * sizeof(float);   // 96KB + 1.5K? -> 98304B
    cudaFuncSetAttribute(gru_persist, cudaFuncAttributeMaxDynamicSharedMemorySize, persistSmem);

    // 1) embedding gathers
    gather_kernel<<<SS * NB, 256>>>(src_ids, embed, Xsrc, SS);
    gather_kernel<<<TDD * NB, 256>>>(trg_ids, embed, Xtrg, TDD);

    // 2) hoisted input projections (gmode=1: write [s][col][n] layout)
    gemm_tf32<<<dim3(CDIV(SS * NB, 128),  CDIV(G3, 128)), 256>>>(Xsrc, Wih_f, bih_f, Gf, SS * NB,  G3, EE, 1, 1);
    gemm_tf32<<<dim3(CDIV(SS * NB, 128),  CDIV(G3, 128)), 256>>>(Xsrc, Wih_b, bih_b, Gb, SS * NB,  G3, EE, 1, 1);
    gemm_tf32<<<dim3(CDIV(TDD * NB, 128), CDIV(G3, 128)), 256>>>(Xtrg, Wih_d, bih_d, Gd, TDD * NB, G3, EE, 1, 1);

    // 3) bidirectional encoder recurrence: ONE persistent launch
    cudaMemsetAsync(ctr, 0, 576 * sizeof(int), 0);
    cudaMemsetAsync(Ht, 0, 2 * 2 * HH * NB * sizeof(float), 0);
    gru_persist<<<128, 512, persistSmem>>>(Gf, Gb, Whh_f, Whh_b, bhh_f, bhh_b,
                                           Ht, ctr, enc, nullptr, SS, 128, 1);

    // 4) attention keys
    gemm_tf32<<<dim3(CDIV(NB * SS, 128), CDIV(HH, 128)), 256>>>(enc, Wk, nullptr, KP, NB * SS, HH, 2 * HH, 0, 0);

    // 5) decoder recurrence: ONE persistent launch
    cudaMemsetAsync(Ht, 0, 2 * 2 * HH * NB * sizeof(float), 0);
    gru_persist<<<64, 512, persistSmem>>>(Gd, Gd, Whh_d, Whh_d, bhh_d, bhh_d,
                                          Ht, ctr + 512, nullptr, Hdec, TDD, 64, 0);

    // 6) batched attention queries + attention + context
    gemm_tf32<<<dim3(CDIV(TDD * NB, 128), CDIV(HH, 128)), 256>>>(Hdec, Wd, battn, Q, TDD * NB, HH, HH, 0, 0);
    attention_kernel<<<TDD * NB, 256>>>(Q, KP, enc, src_mask, vvec, ATTN, CTX);

    // 7) batched generator head
    concat_kernel<<<TDD * NB, 256>>>(Hdec, CTX, CONC);
    gemm_tf32<<<dim3(CDIV(TDD * NB, 128), CDIV(HH, 128)), 256>>>(CONC, W1, b1, GEN1, TDD * NB, HH, G3, 0, 0);
    gemm_tf32<<<dim3(CDIV(TDD * NB, 128), CDIV(VV, 128)), 256>>>(GEN1, W2, b2, LOG, TDD * NB, VV, HH, 0, 0);
    softmax_kernel<<<TDD * NB, 256>>>(LOG, invs);

    // 8) pointer mixture + output assembly
    pgen_kernel<<<(TDD * NB) / 8, 256>>>(Xtrg, CTX, Hdec, Wp, bp, pg);
    outfill_kernel<<<dim3(CDIV(VO, 256), TDD * NB), 256>>>(LOG, pg, invs, out);
    scatter_kernel<<<TDD * NB, 416>>>(ATTN, pg, ptr_idx, out);
}

// round 11
// speedup vs baseline: 4.0902x; 1.2424x over previous
#include <cuda_runtime.h>
#include <cstdint>

#define NB   32      // batch
#define SS   400     // src len
#define TDD  30      // trg len
#define EE   256     // embed
#define HH   512     // HE == HD == 512
#define G3   1536    // 3*H
#define VV   50000
#define OOVV 50
#define VO   50050

#define CDIV(a,b) (((a)+(b)-1)/(b))

// ---------------- scratch (device globals; no allocations allowed) ----------------
__device__ float g_Xsrc[SS * NB * EE];
__device__ float g_Xtrg[TDD * NB * EE];
__device__ float g_Gf[(size_t)SS * NB * G3];    // transposed: [s][col 1536][n 32]
__device__ float g_Gb[(size_t)SS * NB * G3];
__device__ float g_Gd[(size_t)TDD * NB * G3];
__device__ float g_enc[(size_t)NB * SS * 2 * HH];
__device__ float g_KP[(size_t)NB * SS * HH];
__device__ float g_Ht[2 * 2 * HH * NB];         // [parity][dir][k/4][n][4]
__device__ float g_Hdec[TDD * NB * HH];
__device__ float g_Q[TDD * NB * HH];
__device__ float g_ATTN[TDD * NB * SS];
__device__ float g_CTX[TDD * NB * 2 * HH];
__device__ float g_CONC[TDD * NB * G3];
__device__ float g_GEN1[TDD * NB * HH];
__device__ float g_LOG[(size_t)TDD * NB * VV];
__device__ float g_pg[TDD * NB];
__device__ float g_inv[TDD * NB];
__device__ int   g_ctr[576];                    // [0..399] encoder, [512..] decoder

// ---------------- helpers ----------------
__device__ __forceinline__ float fsigmoid(float x) { return 1.f / (1.f + __expf(-x)); }
__device__ __forceinline__ float ftanh(float x) {           // exact-ish (GRU recurrence)
    x = fminf(fmaxf(x, -15.f), 15.f);
    float e2 = __expf(2.f * x);
    return (e2 - 1.f) / (e2 + 1.f);
}
__device__ __forceinline__ float htanh(float x) {           // HW MUFU tanh (attention only)
    float y;
    asm("tanh.approx.f32 %0, %1;" : "=f"(y) : "f"(x));
    return y;
}
__device__ __forceinline__ uint32_t f2tf(float x) {
    uint32_t u;
    asm("cvt.rna.tf32.f32 %0, %1;" : "=r"(u) : "f"(x));
    return u;
}

// ---------------- embedding gather ------------------------------------------------
__global__ void gather_kernel(const int* __restrict__ ids, const float* __restrict__ embed,
                              float* __restrict__ X, int S)
{
    int row = blockIdx.x;                 // s*32 + n
    int s = row >> 5, n = row & 31;
    int id = ids[n * S + s];
    X[(size_t)row * EE + threadIdx.x] = embed[(size_t)id * EE + threadIdx.x];
}

// ---------------- tf32 tensor-core GEMM v2 ----------------------------------------
// C[M,N] = A[M,K] * op(B) + bias.  transB: B is [N,K] else [K,N].  K % 16 == 0.
// BM=128, BN=128, BK=16; 256 threads = 8 warps (2m x 4n), warp tile 64x32.
// gmode: store C[((m>>5)*N + n)*32 + (m&31)]
struct TileRegs { float4 a0, a1; float4 b0, b1; };

__device__ __forceinline__ void ldTile(const float* __restrict__ A, const float* __restrict__ B,
                                       int M, int N, int K, int transB,
                                       int bm, int bn, int k0, int tid, TileRegs& r)
{
    const int arow = tid >> 1, akq = (tid & 1) * 8;
    r.a0 = make_float4(0.f, 0.f, 0.f, 0.f);
    r.a1 = make_float4(0.f, 0.f, 0.f, 0.f);
    if (bm + arow < M) {
        const float* ap = &A[(size_t)(bm + arow) * K + k0 + akq];
        r.a0 = *reinterpret_cast<const float4*>(ap);
        r.a1 = *reinterpret_cast<const float4*>(ap + 4);
    }
    r.b0 = make_float4(0.f, 0.f, 0.f, 0.f);
    r.b1 = make_float4(0.f, 0.f, 0.f, 0.f);
    if (!transB) {
        const int bk = tid >> 4, bnc = (tid & 15) * 8;
        const float* bp = &B[(size_t)(k0 + bk) * N + bn + bnc];
        if (bn + bnc + 7 < N) {
            r.b0 = *reinterpret_cast<const float4*>(bp);
            r.b1 = *reinterpret_cast<const float4*>(bp + 4);
        } else {
            float t[8] = {0.f,0.f,0.f,0.f,0.f,0.f,0.f,0.f};
            for (int i = 0; i < 8; i++) if (bn + bnc + i < N) t[i] = bp[i];
            r.b0 = make_float4(t[0], t[1], t[2], t[3]);
            r.b1 = make_float4(t[4], t[5], t[6], t[7]);
        }
    } else {
        const int n = tid & 127, kh = (tid >> 7) * 8;
        if (bn + n < N) {
            const float* bp = &B[(size_t)(bn + n) * K + k0 + kh];
            r.b0 = *reinterpret_cast<const float4*>(bp);
            r.b1 = *reinterpret_cast<const float4*>(bp + 4);
        }
    }
}

__device__ __forceinline__ void stTile(uint32_t (*As)[20], uint32_t (*Bs)[136],
                                       int transB, int tid, const TileRegs& r)
{
    const int arow = tid >> 1, akq = (tid & 1) * 8;
    As[arow][akq + 0] = f2tf(r.a0.x); As[arow][akq + 1] = f2tf(r.a0.y);
    As[arow][akq + 2] = f2tf(r.a0.z); As[arow][akq + 3] = f2tf(r.a0.w);
    As[arow][akq + 4] = f2tf(r.a1.x); As[arow][akq + 5] = f2tf(r.a1.y);
    As[arow][akq + 6] = f2tf(r.a1.z); As[arow][akq + 7] = f2tf(r.a1.w);
    if (!transB) {
        const int bk = tid >> 4, bnc = (tid & 15) * 8;
        Bs[bk][bnc + 0] = f2tf(r.b0.x); Bs[bk][bnc + 1] = f2tf(r.b0.y);
        Bs[bk][bnc + 2] = f2tf(r.b0.z); Bs[bk][bnc + 3] = f2tf(r.b0.w);
        Bs[bk][bnc + 4] = f2tf(r.b1.x); Bs[bk][bnc + 5] = f2tf(r.b1.y);
        Bs[bk][bnc + 6] = f2tf(r.b1.z); Bs[bk][bnc + 7] = f2tf(r.b1.w);
    } else {
        const int n = tid & 127, kh = (tid >> 7) * 8;
        Bs[kh + 0][n] = f2tf(r.b0.x); Bs[kh + 1][n] = f2tf(r.b0.y);
        Bs[kh + 2][n] = f2tf(r.b0.z); Bs[kh + 3][n] = f2tf(r.b0.w);
        Bs[kh + 4][n] = f2tf(r.b1.x); Bs[kh + 5][n] = f2tf(r.b1.y);
        Bs[kh + 6][n] = f2tf(r.b1.z); Bs[kh + 7][n] = f2tf(r.b1.w);
    }
}

__global__ __launch_bounds__(256) void gemm_tf32(
    const float* __restrict__ A, const float* __restrict__ B,
    const float* __restrict__ bias, float* __restrict__ C,
    int M, int N, int K, int transB, int gmode)
{
    __shared__ uint32_t As[2][128][20];
    __shared__ uint32_t Bs[2][16][136];
    const int bm = blockIdx.x * 128;
    const int bn = blockIdx.y * 128;
    const int tid = threadIdx.x;
    const int lane = tid & 31;
    const int warp = tid >> 5;
    const int wm = warp & 1, wn = warp >> 1;   // warp tile 64m x 32n

    float acc[4][4][4];
#pragma unroll
    for (int mi = 0; mi < 4; mi++)
#pragma unroll
        for (int ni = 0; ni < 4; ni++)
#pragma unroll
            for (int q = 0; q < 4; q++) acc[mi][ni][q] = 0.f;

    const int KT = K >> 4;
    TileRegs tr;
    ldTile(A, B, M, N, K, transB, bm, bn, 0, tid, tr);
    stTile(As[0], Bs[0], transB, tid, tr);
    __syncthreads();

    for (int kt = 0; kt < KT; kt++) {
        const int cur = kt & 1;
        if (kt + 1 < KT)
            ldTile(A, B, M, N, K, transB, bm, bn, (kt + 1) << 4, tid, tr);
#pragma unroll
        for (int ks = 0; ks < 2; ks++) {
            uint32_t af[4][4], bf[4][2];
            const int r0 = wm * 64 + (lane >> 2);
            const int c0 = ks * 8 + (lane & 3);
#pragma unroll
            for (int mi = 0; mi < 4; mi++) {
                const int rr = r0 + mi * 16;
                af[mi][0] = As[cur][rr][c0];
                af[mi][1] = As[cur][rr + 8][c0];
                af[mi][2] = As[cur][rr][c0 + 4];
                af[mi][3] = As[cur][rr + 8][c0 + 4];
            }
#pragma unroll
            for (int ni = 0; ni < 4; ni++) {
                const int nn = wn * 32 + ni * 8 + (lane >> 2);
                bf[ni][0] = Bs[cur][c0][nn];
                bf[ni][1] = Bs[cur][c0 + 4][nn];
            }
#pragma unroll
            for (int mi = 0; mi < 4; mi++)
#pragma unroll
                for (int ni = 0; ni < 4; ni++)
                    asm volatile(
                        "mma.sync.aligned.m16n8k8.row.col.f32.tf32.tf32.f32 "
                        "{%0,%1,%2,%3}, {%4,%5,%6,%7}, {%8,%9}, {%0,%1,%2,%3};"
                        : "+f"(acc[mi][ni][0]), "+f"(acc[mi][ni][1]),
                          "+f"(acc[mi][ni][2]), "+f"(acc[mi][ni][3])
                        : "r"(af[mi][0]), "r"(af[mi][1]), "r"(af[mi][2]), "r"(af[mi][3]),
                          "r"(bf[ni][0]), "r"(bf[ni][1]));
        }
        if (kt + 1 < KT)
            stTile(As[(kt + 1) & 1], Bs[(kt + 1) & 1], transB, tid, tr);
        __syncthreads();
    }

#pragma unroll
    for (int mi = 0; mi < 4; mi++) {
#pragma unroll
        for (int ni = 0; ni < 4; ni++) {
            const int row = bm + wm * 64 + mi * 16 + (lane >> 2);
            const int col = bn + wn * 32 + ni * 8 + (lane & 3) * 2;
#pragma unroll
            for (int h = 0; h < 2; h++) {
                const int m = row + h * 8;
                if (m < M) {
#pragma unroll
                    for (int q = 0; q < 2; q++) {
                        const int n = col + q;
                        if (n < N) {
                            float v = acc[mi][ni][h * 2 + q];
                            if (bias) v += __ldg(&bias[n]);
                            if (gmode) C[((size_t)(m >> 5) * N + n) * 32 + (m & 31)] = v;
                            else       C[(size_t)m * N + n] = v;
                        }
                    }
                }
            }
        }
    }
}

// ---------------- persistent GRU recurrence (tensor-core, 512 threads) ------------
// Per CTA: 8 hidden units (24 gate-rows, padded to 32) x 32 batch, K=512.
// A = Whh slice, step-invariant: pre-swizzled ONCE into SMEM in mma fragment order.
// B = h, loaded per step straight from packed global Ht [k/4][n][4] with coalesced
// 128B __ldcg per fragment register. 16 warps split K (32 each -> 4 k-tiles of 8).
// Partials reduced via stride-33 SMEM; gate phase on warps 0..7 (unit u0+wk),
// hprev carried in a register; release/acquire grid barrier between steps.
__global__ __launch_bounds__(512, 1) void gru_persist(
    const float* __restrict__ G0T, const float* __restrict__ G1T,
    const float* __restrict__ Whh0, const float* __restrict__ Whh1,
    const float* __restrict__ bhh0, const float* __restrict__ bhh1,
    float* __restrict__ Ht, int* ctr,
    float* __restrict__ encOut, float* __restrict__ hdecOut,
    int nSteps, int nCTA, int encMode)
{
    extern __shared__ uint32_t smemU[];
    uint32_t* AF = smemU;                              // [16 warps][8 (mi*4+ki)][32 lanes][4]
    float* rs = reinterpret_cast<float*>(smemU + 16 * 8 * 32 * 4);  // [16*32 rows][33]

    const int dir   = encMode ? (blockIdx.x >> 6) : 0;
    const int utile = blockIdx.x & 63;
    const int u0 = utile * 8;
    const float* Whh = dir ? Whh1 : Whh0;
    const float* bhh = dir ? bhh1 : bhh0;
    const float* GT  = dir ? G1T  : G0T;

    const int tid = threadIdx.x, lane = tid & 31, wk = tid >> 5;   // wk 0..15

    // ---- pre-swizzle A (Whh gate-rows) into fragment order, tf32, once ----
#pragma unroll
    for (int mi = 0; mi < 2; mi++)
#pragma unroll
        for (int ki = 0; ki < 4; ki++)
#pragma unroll
            for (int r = 0; r < 4; r++) {
                int row = mi * 16 + (lane >> 2) + (r & 1) * 8;           // gate-row c
                int col = wk * 32 + ki * 8 + (lane & 3) + (r >> 1) * 4;  // k
                float v = 0.f;
                if (row < 24)
                    v = Whh[((size_t)((row >> 3) * 512 + u0 + (row & 7))) * 512 + col];
                AF[((wk * 8 + mi * 4 + ki) * 32 + lane) * 4 + r] = f2tf(v);
            }
    float b_r = 0.f, b_z = 0.f, b_n = 0.f;
    const int u = u0 + wk;               // valid for wk < 8
    if (wk < 8) {
        b_r = bhh[u];
        b_z = bhh[512 + u];
        b_n = bhh[1024 + u];
    }
    __syncthreads();

    float hprev = 0.f;

    for (int t = 0; t < nSteps; t++) {
        const int p = t & 1;
        const float* Hp = Ht + ((size_t)p * 2 + dir) * HH * NB;
        float*       Hn = Ht + ((size_t)(1 - p) * 2 + dir) * HH * NB;
        const int gidx = dir ? (nSteps - 1 - t) : t;
        const float* Gt = GT + (size_t)gidx * G3 * NB;

        float gir = 0.f, giz = 0.f, gin = 0.f;
        if (wk < 8) {
            gir = __ldg(&Gt[u * 32 + lane]);
            giz = __ldg(&Gt[(512 + u) * 32 + lane]);
            gin = __ldg(&Gt[(1024 + u) * 32 + lane]);
        }

        // ---- B fragments: coalesced 128B loads from packed Ht ----
        uint32_t bReg[4][4][2];          // [ni][ki][2]
        const int kq = wk * 8;           // (wk*32)>>2
#pragma unroll
        for (int ki = 0; ki < 4; ki++)
#pragma unroll
            for (int ni = 0; ni < 4; ni++) {
                float v0 = __ldcg(&Hp[(kq + ki * 2) * 128 + ni * 32 + lane]);
                float v1 = __ldcg(&Hp[(kq + ki * 2 + 1) * 128 + ni * 32 + lane]);
                bReg[ni][ki][0] = f2tf(v0);
                bReg[ni][ki][1] = f2tf(v1);
            }

        float acc[2][4][4];
#pragma unroll
        for (int mi = 0; mi < 2; mi++)
#pragma unroll
            for (int ni = 0; ni < 4; ni++)
#pragma unroll
                for (int q = 0; q < 4; q++) acc[mi][ni][q] = 0.f;

#pragma unroll
        for (int mi = 0; mi < 2; mi++)
#pragma unroll
            for (int ki = 0; ki < 4; ki++) {
                uint4 a = *reinterpret_cast<const uint4*>(
                    &AF[((wk * 8 + mi * 4 + ki) * 32 + lane) * 4]);
#pragma unroll
                for (int ni = 0; ni < 4; ni++)
                    asm volatile(
                        "mma.sync.aligned.m16n8k8.row.col.f32.tf32.tf32.f32 "
                        "{%0,%1,%2,%3}, {%4,%5,%6,%7}, {%8,%9}, {%0,%1,%2,%3};"
                        : "+f"(acc[mi][ni][0]), "+f"(acc[mi][ni][1]),
                          "+f"(acc[mi][ni][2]), "+f"(acc[mi][ni][3])
                        : "r"(a.x), "r"(a.y), "r"(a.z), "r"(a.w),
                          "r"(bReg[ni][ki][0]), "r"(bReg[ni][ki][1]));
            }

        // ---- store K-partials to SMEM (stride 33) ----
        {
            const int row0 = lane >> 2, col0 = 2 * (lane & 3);
#pragma unroll
            for (int mi = 0; mi < 2; mi++)
#pragma unroll
                for (int ni = 0; ni < 4; ni++) {
                    float* base = &rs[(wk * 32 + mi * 16 + row0) * 33 + ni * 8 + col0];
                    base[0]          = acc[mi][ni][0];
                    base[1]          = acc[mi][ni][1];
                    base[33 * 8]     = acc[mi][ni][2];
                    base[33 * 8 + 1] = acc[mi][ni][3];
                }
        }
        __syncthreads();

        // ---- gate phase: warp wk<8 owns unit u = u0+wk, lane = n ----
        if (wk < 8) {
            float ar = 0.f, az = 0.f, an = 0.f;
#pragma unroll
            for (int w2 = 0; w2 < 16; w2++) {
                ar += rs[(w2 * 32 + wk) * 33 + lane];
                az += rs[(w2 * 32 + 8 + wk) * 33 + lane];
                an += rs[(w2 * 32 + 16 + wk) * 33 + lane];
            }
            float r = fsigmoid(gir + ar + b_r);
            float z = fsigmoid(giz + az + b_z);
            float nn = ftanh(gin + (an + b_n) * r);
            float hnew = (1.f - z) * nn + z * hprev;
            hprev = hnew;
            __stcg(&Hn[(u >> 2) * 128 + lane * 4 + (u & 3)], hnew);
            if (encMode) {
                int s = dir ? (nSteps - 1 - t) : t;
                encOut[(size_t)lane * SS * 1024 + (size_t)s * 1024 + dir * 512 + u] = hnew;
            } else {
                hdecOut[(size_t)t * NB * HH + (size_t)lane * HH + u] = hnew;
            }
        }
        __syncthreads();

        if (t + 1 < nSteps) {
            if (tid == 0) {
                int* a = &ctr[t];
                asm volatile("red.release.gpu.global.add.u32 [%0], 1;" :: "l"(a) : "memory");
                unsigned v;
                do {
                    asm volatile("ld.acquire.gpu.global.u32 %0, [%1];" : "=r"(v) : "l"(a) : "memory");
                } while (v < (unsigned)nCTA);
            }
            __syncthreads();
        }
    }
}

// ---------------- batched attention (one CTA per (t,n) row) -----------------------
__global__ void attention_kernel(const float* __restrict__ Q, const float* __restrict__ KP,
                                 const float* __restrict__ ENC, const float* __restrict__ mask,
                                 const float* __restrict__ vvec, float* __restrict__ ATTN,
                                 float* __restrict__ CTX)
{
    const int row = blockIdx.x;          // t*32 + n
    const int n = row & 31;
    const int tid = threadIdx.x, lane = tid & 31, warp = tid >> 5;
    __shared__ float qs[HH], vs[HH], es[SS], red[256];

    for (int i = tid; i < HH; i += 256) { qs[i] = Q[(size_t)row * HH + i]; vs[i] = vvec[i]; }
    __syncthreads();

    for (int s = warp; s < SS; s += 8) {
        const float* kp = KP + ((size_t)n * SS + s) * HH;
        float part = 0.f;
        for (int d = lane; d < HH; d += 32)
            part += htanh(kp[d] + qs[d]) * vs[d];
#pragma unroll
        for (int o = 16; o; o >>= 1) part += __shfl_xor_sync(0xffffffffu, part, o);
        if (lane == 0) es[s] = part + (1.f - mask[n * SS + s]) * (-1e10f);
    }
    __syncthreads();

    float m = -1e30f;
    for (int s = tid; s < SS; s += 256) m = fmaxf(m, es[s]);
    red[tid] = m; __syncthreads();
    for (int st = 128; st; st >>= 1) { if (tid < st) red[tid] = fmaxf(red[tid], red[tid + st]); __syncthreads(); }
    float mx = red[0]; __syncthreads();

    float sum = 0.f;
    for (int s = tid; s < SS; s += 256) { float e = __expf(es[s] - mx); es[s] = e; sum += e; }
    red[tid] = sum; __syncthreads();
    for (int st = 128; st; st >>= 1) { if (tid < st) red[tid] += red[tid + st]; __syncthreads(); }
    float inv = 1.f / red[0]; __syncthreads();

    for (int s = tid; s < SS; s += 256) { float a = es[s] * inv; es[s] = a; ATTN[(size_t)row * SS + s] = a; }
    __syncthreads();

    float a0 = 0.f, a1 = 0.f, a2 = 0.f, a3 = 0.f;
    for (int s = 0; s < SS; s++) {
        float a = es[s];
        const float* er = ENC + ((size_t)n * SS + s) * 1024;
        a0 += a * er[tid];
        a1 += a * er[tid + 256];
        a2 += a * er[tid + 512];
        a3 += a * er[tid + 768];
    }
    CTX[(size_t)row * 1024 + tid]       = a0;
    CTX[(size_t)row * 1024 + tid + 256] = a1;
    CTX[(size_t)row * 1024 + tid + 512] = a2;
    CTX[(size_t)row * 1024 + tid + 768] = a3;
}

// ---------------- concat [h, ctx] --------------------------------------------------
__global__ void concat_kernel(const float* __restrict__ H, const float* __restrict__ CTX,
                              float* __restrict__ C)
{
    int row = blockIdx.x;
    for (int i = threadIdx.x; i < G3; i += 256)
        C[(size_t)row * G3 + i] = (i < HH) ? H[(size_t)row * HH + i]
                                           : CTX[(size_t)row * 1024 + (i - HH)];
}

// ---------------- row softmax over V (stores exp, and 1/sum) ----------------------
__global__ void softmax_kernel(float* __restrict__ LOG, float* __restrict__ invs)
{
    const int row = blockIdx.x, tid = threadIdx.x;
    float* p = LOG + (size_t)row * VV;
    __shared__ float red[256];
    float m = -1e30f;
    for (int i = tid; i < VV; i += 256) m = fmaxf(m, p[i]);
    red[tid] = m; __syncthreads();
    for (int st = 128; st; st >>= 1) { if (tid < st) red[tid] = fmaxf(red[tid], red[tid + st]); __syncthreads(); }
    float mx = red[0]; __syncthreads();
    float sum = 0.f;
    for (int i = tid; i < VV; i += 256) { float e = __expf(p[i] - mx); p[i] = e; sum += e; }
    red[tid] = sum; __syncthreads();
    for (int st = 128; st; st >>= 1) { if (tid < st) red[tid] += red[tid + st]; __syncthreads(); }
    if (tid == 0) invs[row] = 1.f / red[0];
}

// ---------------- p_gen = sigmoid([xi, ctx, h] @ Wp + bp) -------------------------
__global__ void pgen_kernel(const float* __restrict__ Xtrg, const float* __restrict__ CTX,
                            const float* __restrict__ H, const float* __restrict__ Wp,
                            const float* __restrict__ bp, float* __restrict__ pg)
{
    const int warp = threadIdx.x >> 5, lane = threadIdx.x & 31;
    const int row = blockIdx.x * 8 + warp;
    float part = 0.f;
    for (int k = lane; k < 1792; k += 32) {
        float xv;
        if (k < 256)       xv = Xtrg[(size_t)row * EE + k];
        else if (k < 1280) xv = CTX[(size_t)row * 1024 + (k - 256)];
        else               xv = H[(size_t)row * HH + (k - 1280)];
        part += xv * Wp[k];
    }
#pragma unroll
    for (int o = 16; o; o >>= 1) part += __shfl_xor_sync(0xffffffffu, part, o);
    if (lane == 0) pg[row] = fsigmoid(part + bp[0]);
}

// ---------------- out = p_gen * gen_ext (OOV region zeroed) -----------------------
__global__ void outfill_kernel(const float* __restrict__ LOG, const float* __restrict__ pg,
                               const float* __restrict__ invs, float* __restrict__ out)
{
    const int row = blockIdx.y;          // t*32 + n
    const int t = row / NB, n = row % NB;
    const int vv = blockIdx.x * 256 + threadIdx.x;
    if (vv >= VO) return;
    float val = 0.f;
    if (vv < VV) val = pg[row] * invs[row] * LOG[(size_t)row * VV + vv];
    out[((size_t)n * TDD + t) * VO + vv] = val;
}

// ---------------- deterministic scatter-add of (1-p)*attn at ptr indices ----------
__global__ void scatter_kernel(const float* __restrict__ ATTN, const float* __restrict__ pg,
                               const int* __restrict__ ptr_idx, float* __restrict__ out)
{
    const int row = blockIdx.x;          // t*32 + n
    const int t = row / NB, n = row % NB;
    __shared__ int   sidx[SS];
    __shared__ float sw[SS];
    const int s = threadIdx.x;
    const float om = 1.f - pg[row];
    if (s < SS) {
        sidx[s] = ptr_idx[n * SS + s];
        sw[s]   = om * ATTN[(size_t)row * SS + s];
    }
    __syncthreads();
    if (s < SS) {
        int my = sidx[s];
        bool first = true;
        for (int s2 = 0; s2 < s; s2++) if (sidx[s2] == my) { first = false; break; }
        if (first) {
            float val = sw[s];
            for (int s2 = s + 1; s2 < SS; s2++) if (sidx[s2] == my) val += sw[s2];
            out[((size_t)n * TDD + t) * VO + my] += val;   // rows exclusive -> no atomics
        }
    }
}

// ---------------- launch --------------------------------------------------------
extern "C" void kernel_launch(void* const* d_in, const int* in_sizes, int n_in,
                              void* d_out, int out_size)
{
    const int*   src_ids  = (const int*)  d_in[0];
    const float* src_mask = (const float*)d_in[1];
    const int*   trg_ids  = (const int*)  d_in[2];
    const int*   ptr_idx  = (const int*)  d_in[3];
    const float* embed    = (const float*)d_in[4];
    const float* Wih_f = (const float*)d_in[5],  *Whh_f = (const float*)d_in[6];
    const float* bih_f = (const float*)d_in[7],  *bhh_f = (const float*)d_in[8];
    const float* Wih_b = (const float*)d_in[9],  *Whh_b = (const float*)d_in[10];
    const float* bih_b = (const float*)d_in[11], *bhh_b = (const float*)d_in[12];
    const float* Wih_d = (const float*)d_in[13], *Whh_d = (const float*)d_in[14];
    const float* bih_d = (const float*)d_in[15], *bhh_d = (const float*)d_in[16];
    const float* Wk    = (const float*)d_in[17], *Wd    = (const float*)d_in[18];
    const float* battn = (const float*)d_in[19], *vvec  = (const float*)d_in[20];
    const float* W1    = (const float*)d_in[21], *b1    = (const float*)d_in[22];
    const float* W2    = (const float*)d_in[23], *b2    = (const float*)d_in[24];
    const float* Wp    = (const float*)d_in[25], *bp    = (const float*)d_in[26];
    float* out = (float*)d_out;

    float *Xsrc, *Xtrg, *Gf, *Gb, *Gd, *enc, *KP, *Ht, *Hdec, *Q, *ATTN, *CTX,
          *CONC, *GEN1, *LOG, *pg, *invs;
    int* ctr;
    cudaGetSymbolAddress((void**)&Xsrc, g_Xsrc);
    cudaGetSymbolAddress((void**)&Xtrg, g_Xtrg);
    cudaGetSymbolAddress((void**)&Gf,   g_Gf);
    cudaGetSymbolAddress((void**)&Gb,   g_Gb);
    cudaGetSymbolAddress((void**)&Gd,   g_Gd);
    cudaGetSymbolAddress((void**)&enc,  g_enc);
    cudaGetSymbolAddress((void**)&KP,   g_KP);
    cudaGetSymbolAddress((void**)&Ht,   g_Ht);
    cudaGetSymbolAddress((void**)&Hdec, g_Hdec);
    cudaGetSymbolAddress((void**)&Q,    g_Q);
    cudaGetSymbolAddress((void**)&ATTN, g_ATTN);
    cudaGetSymbolAddress((void**)&CTX,  g_CTX);
    cudaGetSymbolAddress((void**)&CONC, g_CONC);
    cudaGetSymbolAddress((void**)&GEN1, g_GEN1);
    cudaGetSymbolAddress((void**)&LOG,  g_LOG);
    cudaGetSymbolAddress((void**)&pg,   g_pg);
    cudaGetSymbolAddress((void**)&invs, g_inv);
    cudaGetSymbolAddress((void**)&ctr,  g_ctr);

    // AF: 16*8*32*4 u32 (64KB) + rs: 16*32*33 f32 (66KB)
    const int persistSmem = (16 * 8 * 32 * 4) * 4 + (16 * 32 * 33) * 4;
    cudaFuncSetAttribute(gru_persist, cudaFuncAttributeMaxDynamicSharedMemorySize, persistSmem);

    // 1) embedding gathers
    gather_kernel<<<SS * NB, 256>>>(src_ids, embed, Xsrc, SS);
    gather_kernel<<<TDD * NB, 256>>>(trg_ids, embed, Xtrg, TDD);

    // 2) hoisted input projections (gmode=1: write [s][col][n] layout)
    gemm_tf32<<<dim3(CDIV(SS * NB, 128),  CDIV(G3, 128)), 256>>>(Xsrc, Wih_f, bih_f, Gf, SS * NB,  G3, EE, 1, 1);
    gemm_tf32<<<dim3(CDIV(SS * NB, 128),  CDIV(G3, 128)), 256>>>(Xsrc, Wih_b, bih_b, Gb, SS * NB,  G3, EE, 1, 1);
    gemm_tf32<<<dim3(CDIV(TDD * NB, 128), CDIV(G3, 128)), 256>>>(Xtrg, Wih_d, bih_d, Gd, TDD * NB, G3, EE, 1, 1);

    // 3) bidirectional encoder recurrence: ONE persistent launch
    cudaMemsetAsync(ctr, 0, 576 * sizeof(int), 0);
    cudaMemsetAsync(Ht, 0, 2 * 2 * HH * NB * sizeof(float), 0);
    gru_persist<<<128, 512, persistSmem>>>(Gf, Gb, Whh_f, Whh_b, bhh_f, bhh_b,
                                           Ht, ctr, enc, nullptr, SS, 128, 1);

    // 4) attention keys
    gemm_tf32<<<dim3(CDIV(NB * SS, 128), CDIV(HH, 128)), 256>>>(enc, Wk, nullptr, KP, NB * SS, HH, 2 * HH, 0, 0);

    // 5) decoder recurrence: ONE persistent launch
    cudaMemsetAsync(Ht, 0, 2 * 2 * HH * NB * sizeof(float), 0);
    gru_persist<<<64, 512, persistSmem>>>(Gd, Gd, Whh_d, Whh_d, bhh_d, bhh_d,
                                          Ht, ctr + 512, nullptr, Hdec, TDD, 64, 0);

    // 6) batched attention queries + attention + context
    gemm_tf32<<<dim3(CDIV(TDD * NB, 128), CDIV(HH, 128)), 256>>>(Hdec, Wd, battn, Q, TDD * NB, HH, HH, 0, 0);
    attention_kernel<<<TDD * NB, 256>>>(Q, KP, enc, src_mask, vvec, ATTN, CTX);

    // 7) batched generator head
    concat_kernel<<<TDD * NB, 256>>>(Hdec, CTX, CONC);
    gemm_tf32<<<dim3(CDIV(TDD * NB, 128), CDIV(HH, 128)), 256>>>(CONC, W1, b1, GEN1, TDD * NB, HH, G3, 0, 0);
    gemm_tf32<<<dim3(CDIV(TDD * NB, 128), CDIV(VV, 128)), 256>>>(GEN1, W2, b2, LOG, TDD * NB, VV, HH, 0, 0);
    softmax_kernel<<<TDD * NB, 256>>>(LOG, invs);

    // 8) pointer mixture + output assembly
    pgen_kernel<<<(TDD * NB) / 8, 256>>>(Xtrg, CTX, Hdec, Wp, bp, pg);
    outfill_kernel<<<dim3(CDIV(VO, 256), TDD * NB), 256>>>(LOG, pg, invs, out);
    scatter_kernel<<<TDD * NB, 416>>>(ATTN, pg, ptr_idx, out);
}

// round 13
// speedup vs baseline: 4.5785x; 1.1194x over previous
#include <cuda_runtime.h>
#include <cstdint>

#define NB   32      // batch
#define SS   400     // src len
#define TDD  30      // trg len
#define EE   256     // embed
#define HH   512     // HE == HD == 512
#define G3   1536    // 3*H
#define VV   50000
#define OOVV 50
#define VO   50050

#define CDIV(a,b) (((a)+(b)-1)/(b))

// ---------------- scratch (device globals; no allocations allowed) ----------------
__device__ float g_Xsrc[SS * NB * EE];
__device__ float g_Xtrg[TDD * NB * EE];
__device__ float g_Gf[(size_t)SS * NB * G3];    // transposed: [s][col 1536][n 32]
__device__ float g_Gb[(size_t)SS * NB * G3];
__device__ float g_Gd[(size_t)TDD * NB * G3];
__device__ float g_enc[(size_t)NB * SS * 2 * HH];
__device__ float g_KP[(size_t)NB * SS * HH];
__device__ float g_Ht[2 * 2 * HH * NB];         // [parity][dir][k/4][n][4]
__device__ float g_Hdec[TDD * NB * HH];
__device__ float g_Q[TDD * NB * HH];
__device__ float g_ATTN[TDD * NB * SS];
__device__ float g_CTX[TDD * NB * 2 * HH];
__device__ float g_CONC[TDD * NB * G3];
__device__ float g_GEN1[TDD * NB * HH];
__device__ float g_LOG[(size_t)TDD * NB * VV];
__device__ float g_pg[TDD * NB];
__device__ float g_inv[TDD * NB];
__device__ int   g_ctr[1024];   // enc fwd [0..399], enc bwd [400..799], dec [830..859]

// ---------------- helpers ----------------
__device__ __forceinline__ float fsigmoid(float x) { return 1.f / (1.f + __expf(-x)); }
__device__ __forceinline__ float ftanh(float x) {           // exact-ish (GRU recurrence)
    x = fminf(fmaxf(x, -15.f), 15.f);
    float e2 = __expf(2.f * x);
    return (e2 - 1.f) / (e2 + 1.f);
}
__device__ __forceinline__ float htanh(float x) {           // HW MUFU tanh (attention only)
    float y;
    asm("tanh.approx.f32 %0, %1;" : "=f"(y) : "f"(x));
    return y;
}
__device__ __forceinline__ uint32_t f2tf(float x) {
    uint32_t u;
    asm("cvt.rna.tf32.f32 %0, %1;" : "=r"(u) : "f"(x));
    return u;
}
__device__ __forceinline__ void cpa16(uint32_t dst, const void* src, int sz) {
    asm volatile("cp.async.cg.shared.global [%0], [%1], 16, %2;"
                 :: "r"(dst), "l"(src), "r"(sz) : "memory");
}

// ---------------- embedding gather ------------------------------------------------
__global__ void gather_kernel(const int* __restrict__ ids, const float* __restrict__ embed,
                              float* __restrict__ X, int S)
{
    int row = blockIdx.x;                 // s*32 + n
    int s = row >> 5, n = row & 31;
    int id = ids[n * S + s];
    X[(size_t)row * EE + threadIdx.x] = embed[(size_t)id * EE + threadIdx.x];
}

// ---------------- tf32 tensor-core GEMM v3: cp.async 3-stage ----------------------
// C[M,N] = A[M,K] * op(B) + bias.  transB: B is [N,K] else [K,N].  K % 16 == 0.
// BM=128, BN=128, BK=16; 256 threads = 8 warps (2m x 4n), warp tile 64x32.
// fp32 bits fed to mma.tf32 directly (HW truncation). transB tiles stored like A
// (row-major K-contig, [128][20]); non-transB B tile [16][136]. All cp.async 16B.
// gmode: store C[((m>>5)*N + n)*32 + (m&31)]
__global__ __launch_bounds__(256) void gemm_tf32(
    const float* __restrict__ A, const float* __restrict__ B,
    const float* __restrict__ bias, float* __restrict__ C,
    int M, int N, int K, int transB, int gmode)
{
    extern __shared__ float sm[];        // 3 stages x (A 2560 + B 2560) floats
    const int bm = blockIdx.x * 128;
    const int bn = blockIdx.y * 128;
    const int tid = threadIdx.x;
    const int lane = tid & 31;
    const int warp = tid >> 5;
    const int wm = warp & 1, wn = warp >> 1;
    const uint32_t smBase = (uint32_t)__cvta_generic_to_shared(sm);

    float acc[4][4][4];
#pragma unroll
    for (int mi = 0; mi < 4; mi++)
#pragma unroll
        for (int ni = 0; ni < 4; ni++)
#pragma unroll
            for (int q = 0; q < 4; q++) acc[mi][ni][q] = 0.f;

    const int KT = K >> 4;

    auto issue = [&](int st, int k0) {   // st MUST be a stage index 0..2
        const uint32_t AsU = smBase + (uint32_t)st * 5120u * 4u;
        const uint32_t BsU = AsU + 2560u * 4u;
#pragma unroll
        for (int c = 0; c < 2; c++) {
            int idx = c * 256 + tid;
            int row = idx >> 2, cq = idx & 3;
            const float* src = A + (size_t)(bm + row) * K + k0 + cq * 4;
            int sz = (bm + row < M) ? 16 : 0;
            if (!sz) src = A;
            cpa16(AsU + (uint32_t)(row * 20 + cq * 4) * 4u, src, sz);
        }
        if (!transB) {
#pragma unroll
            for (int c = 0; c < 2; c++) {
                int idx = c * 256 + tid;
                int row = idx >> 5, cq = idx & 31;
                int col = bn + cq * 4;
                const float* src = B + (size_t)(k0 + row) * N + col;
                int rem = N - col;
                int sz = rem >= 4 ? 16 : (rem > 0 ? rem * 4 : 0);
                if (!sz) src = B;
                cpa16(BsU + (uint32_t)(row * 136 + cq * 4) * 4u, src, sz);
            }
        } else {
#pragma unroll
            for (int c = 0; c < 2; c++) {
                int idx = c * 256 + tid;
                int row = idx >> 2, cq = idx & 3;
                const float* src = B + (size_t)(bn + row) * K + k0 + cq * 4;
                int sz = (bn + row < N) ? 16 : 0;
                if (!sz) src = B;
                cpa16(BsU + (uint32_t)(row * 20 + cq * 4) * 4u, src, sz);
            }
        }
        asm volatile("cp.async.commit_group;" ::: "memory");
    };

    issue(0, 0);
    if (KT > 1) issue(1, 16);
    else asm volatile("cp.async.commit_group;" ::: "memory");

    for (int kt = 0; kt < KT; kt++) {
        const int st = kt % 3;
        asm volatile("cp.async.wait_group 1;" ::: "memory");
        __syncthreads();
        const uint32_t* As = reinterpret_cast<const uint32_t*>(sm + st * 5120);
        const uint32_t* Bs = As + 2560;
#pragma unroll
        for (int ks = 0; ks < 2; ks++) {
            uint32_t af[4][4], bf[4][2];
            const int r0 = wm * 64 + (lane >> 2);
            const int c0 = ks * 8 + (lane & 3);
#pragma unroll
            for (int mi = 0; mi < 4; mi++) {
                const int rr = r0 + mi * 16;
                af[mi][0] = As[rr * 20 + c0];
                af[mi][1] = As[(rr + 8) * 20 + c0];
                af[mi][2] = As[rr * 20 + c0 + 4];
                af[mi][3] = As[(rr + 8) * 20 + c0 + 4];
            }
#pragma unroll
            for (int ni = 0; ni < 4; ni++) {
                const int nn = wn * 32 + ni * 8 + (lane >> 2);
                if (transB) {
                    bf[ni][0] = Bs[nn * 20 + c0];
                    bf[ni][1] = Bs[nn * 20 + c0 + 4];
                } else {
                    bf[ni][0] = Bs[c0 * 136 + nn];
                    bf[ni][1] = Bs[(c0 + 4) * 136 + nn];
                }
            }
#pragma unroll
            for (int mi = 0; mi < 4; mi++)
#pragma unroll
                for (int ni = 0; ni < 4; ni++)
                    asm volatile(
                        "mma.sync.aligned.m16n8k8.row.col.f32.tf32.tf32.f32 "
                        "{%0,%1,%2,%3}, {%4,%5,%6,%7}, {%8,%9}, {%0,%1,%2,%3};"
                        : "+f"(acc[mi][ni][0]), "+f"(acc[mi][ni][1]),
                          "+f"(acc[mi][ni][2]), "+f"(acc[mi][ni][3])
                        : "r"(af[mi][0]), "r"(af[mi][1]), "r"(af[mi][2]), "r"(af[mi][3]),
                          "r"(bf[ni][0]), "r"(bf[ni][1]));
        }
        if (kt + 2 < KT) issue((kt + 2) % 3, (kt + 2) << 4);   // FIX: stage = (kt+2)%3
        else asm volatile("cp.async.commit_group;" ::: "memory");
    }

#pragma unroll
    for (int mi = 0; mi < 4; mi++) {
#pragma unroll
        for (int ni = 0; ni < 4; ni++) {
            const int row = bm + wm * 64 + mi * 16 + (lane >> 2);
            const int col = bn + wn * 32 + ni * 8 + (lane & 3) * 2;
#pragma unroll
            for (int h = 0; h < 2; h++) {
                const int m = row + h * 8;
                if (m < M) {
#pragma unroll
                    for (int q = 0; q < 2; q++) {
                        const int n = col + q;
                        if (n < N) {
                            float v = acc[mi][ni][h * 2 + q];
                            if (bias) v += __ldg(&bias[n]);
                            if (gmode) C[((size_t)(m >> 5) * N + n) * 32 + (m & 31)] = v;
                            else       C[(size_t)m * N + n] = v;
                        }
                    }
                }
            }
        }
    }
}

// ---------------- persistent GRU recurrence (tensor-core, 512 threads) ------------
// Per CTA: 8 hidden units (24 gate-rows, padded to 32) x 32 batch, K=512.
// A = Whh slice pre-swizzled once into SMEM fragment order. B = h loaded per step
// from packed global Ht [k/4][n][4] with coalesced 128B __ldcg. 16 warps split K.
// Per-direction grid barrier (fwd/bwd independent): dir0 -> ctr[t], dir1 -> ctr[nSteps+t].
__global__ __launch_bounds__(512, 1) void gru_persist(
    const float* __restrict__ G0T, const float* __restrict__ G1T,
    const float* __restrict__ Whh0, const float* __restrict__ Whh1,
    const float* __restrict__ bhh0, const float* __restrict__ bhh1,
    float* __restrict__ Ht, int* ctr,
    float* __restrict__ encOut, float* __restrict__ hdecOut,
    int nSteps, int nCTA, int encMode)
{
    extern __shared__ uint32_t smemU[];
    uint32_t* AF = smemU;                              // [16 warps][8 (mi*4+ki)][32 lanes][4]
    float* rs = reinterpret_cast<float*>(smemU + 16 * 8 * 32 * 4);  // [16*32 rows][33]

    const int dir   = encMode ? (blockIdx.x >> 6) : 0;
    const int utile = blockIdx.x & 63;
    const int u0 = utile * 8;
    const float* Whh = dir ? Whh1 : Whh0;
    const float* bhh = dir ? bhh1 : bhh0;
    const float* GT  = dir ? G1T  : G0T;

    const int tid = threadIdx.x, lane = tid & 31, wk = tid >> 5;   // wk 0..15

    // ---- pre-swizzle A (Whh gate-rows) into fragment order, tf32, once ----
#pragma unroll
    for (int mi = 0; mi < 2; mi++)
#pragma unroll
        for (int ki = 0; ki < 4; ki++)
#pragma unroll
            for (int r = 0; r < 4; r++) {
                int row = mi * 16 + (lane >> 2) + (r & 1) * 8;           // gate-row c
                int col = wk * 32 + ki * 8 + (lane & 3) + (r >> 1) * 4;  // k
                float v = 0.f;
                if (row < 24)
                    v = Whh[((size_t)((row >> 3) * 512 + u0 + (row & 7))) * 512 + col];
                AF[((wk * 8 + mi * 4 + ki) * 32 + lane) * 4 + r] = f2tf(v);
            }
    float b_r = 0.f, b_z = 0.f, b_n = 0.f;
    const int u = u0 + wk;               // valid for wk < 8
    if (wk < 8) {
        b_r = bhh[u];
        b_z = bhh[512 + u];
        b_n = bhh[1024 + u];
    }
    __syncthreads();

    float hprev = 0.f;

    for (int t = 0; t < nSteps; t++) {
        const int p = t & 1;
        const float* Hp = Ht + ((size_t)p * 2 + dir) * HH * NB;
        float*       Hn = Ht + ((size_t)(1 - p) * 2 + dir) * HH * NB;
        const int gidx = dir ? (nSteps - 1 - t) : t;
        const float* Gt = GT + (size_t)gidx * G3 * NB;

        float gir = 0.f, giz = 0.f, gin = 0.f;
        if (wk < 8) {
            gir = __ldg(&Gt[u * 32 + lane]);
            giz = __ldg(&Gt[(512 + u) * 32 + lane]);
            gin = __ldg(&Gt[(1024 + u) * 32 + lane]);
        }

        // ---- B fragments: coalesced 128B loads from packed Ht ----
        uint32_t bReg[4][4][2];          // [ni][ki][2]
        const int kq = wk * 8;           // (wk*32)>>2
#pragma unroll
        for (int ki = 0; ki < 4; ki++)
#pragma unroll
            for (int ni = 0; ni < 4; ni++) {
                float v0 = __ldcg(&Hp[(kq + ki * 2) * 128 + ni * 32 + lane]);
                float v1 = __ldcg(&Hp[(kq + ki * 2 + 1) * 128 + ni * 32 + lane]);
                bReg[ni][ki][0] = f2tf(v0);
                bReg[ni][ki][1] = f2tf(v1);
            }

        float acc[2][4][4];
#pragma unroll
        for (int mi = 0; mi < 2; mi++)
#pragma unroll
            for (int ni = 0; ni < 4; ni++)
#pragma unroll
                for (int q = 0; q < 4; q++) acc[mi][ni][q] = 0.f;

#pragma unroll
        for (int mi = 0; mi < 2; mi++)
#pragma unroll
            for (int ki = 0; ki < 4; ki++) {
                uint4 a = *reinterpret_cast<const uint4*>(
                    &AF[((wk * 8 + mi * 4 + ki) * 32 + lane) * 4]);
#pragma unroll
                for (int ni = 0; ni < 4; ni++)
                    asm volatile(
                        "mma.sync.aligned.m16n8k8.row.col.f32.tf32.tf32.f32 "
                        "{%0,%1,%2,%3}, {%4,%5,%6,%7}, {%8,%9}, {%0,%1,%2,%3};"
                        : "+f"(acc[mi][ni][0]), "+f"(acc[mi][ni][1]),
                          "+f"(acc[mi][ni][2]), "+f"(acc[mi][ni][3])
                        : "r"(a.x), "r"(a.y), "r"(a.z), "r"(a.w),
                          "r"(bReg[ni][ki][0]), "r"(bReg[ni][ki][1]));
            }

        // ---- store K-partials to SMEM (stride 33) ----
        {
            const int row0 = lane >> 2, col0 = 2 * (lane & 3);
#pragma unroll
            for (int mi = 0; mi < 2; mi++)
#pragma unroll
                for (int ni = 0; ni < 4; ni++) {
                    float* base = &rs[(wk * 32 + mi * 16 + row0) * 33 + ni * 8 + col0];
                    base[0]          = acc[mi][ni][0];
                    base[1]          = acc[mi][ni][1];
                    base[33 * 8]     = acc[mi][ni][2];
                    base[33 * 8 + 1] = acc[mi][ni][3];
                }
        }
        __syncthreads();

        // ---- gate phase: warp wk<8 owns unit u = u0+wk, lane = n ----
        if (wk < 8) {
            float ar = 0.f, az = 0.f, an = 0.f;
#pragma unroll
            for (int w2 = 0; w2 < 16; w2++) {
                ar += rs[(w2 * 32 + wk) * 33 + lane];
                az += rs[(w2 * 32 + 8 + wk) * 33 + lane];
                an += rs[(w2 * 32 + 16 + wk) * 33 + lane];
            }
            float r = fsigmoid(gir + ar + b_r);
            float z = fsigmoid(giz + az + b_z);
            float nn = ftanh(gin + (an + b_n) * r);
            float hnew = (1.f - z) * nn + z * hprev;
            hprev = hnew;
            __stcg(&Hn[(u >> 2) * 128 + lane * 4 + (u & 3)], hnew);
            if (encMode) {
                int s = dir ? (nSteps - 1 - t) : t;
                encOut[(size_t)lane * SS * 1024 + (size_t)s * 1024 + dir * 512 + u] = hnew;
            } else {
                hdecOut[(size_t)t * NB * HH + (size_t)lane * HH + u] = hnew;
            }
        }
        __syncthreads();

        if (t + 1 < nSteps) {
            if (tid == 0) {
                int* a = &ctr[dir ? (nSteps + t) : t];
                asm volatile("red.release.gpu.global.add.u32 [%0], 1;" :: "l"(a) : "memory");
                unsigned v;
                do {
                    asm volatile("ld.acquire.gpu.global.u32 %0, [%1];" : "=r"(v) : "l"(a) : "memory");
                } while (v < (unsigned)nCTA);
            }
            __syncthreads();
        }
    }
}

// ---------------- batched attention (one CTA per (t,n) row) -----------------------
__global__ void attention_kernel(const float* __restrict__ Q, const float* __restrict__ KP,
                                 const float* __restrict__ ENC, const float* __restrict__ mask,
                                 const float* __restrict__ vvec, float* __restrict__ ATTN,
                                 float* __restrict__ CTX)
{
    const int row = blockIdx.x;          // t*32 + n
    const int n = row & 31;
    const int tid = threadIdx.x, lane = tid & 31, warp = tid >> 5;
    __shared__ float qs[HH], vs[HH], es[SS], red[256];

    for (int i = tid; i < HH; i += 256) { qs[i] = Q[(size_t)row * HH + i]; vs[i] = vvec[i]; }
    __syncthreads();

    for (int s = warp; s < SS; s += 8) {
        const float* kp = KP + ((size_t)n * SS + s) * HH;
        float part = 0.f;
        for (int d = lane; d < HH; d += 32)
            part += htanh(kp[d] + qs[d]) * vs[d];
#pragma unroll
        for (int o = 16; o; o >>= 1) part += __shfl_xor_sync(0xffffffffu, part, o);
        if (lane == 0) es[s] = part + (1.f - mask[n * SS + s]) * (-1e10f);
    }
    __syncthreads();

    float m = -1e30f;
    for (int s = tid; s < SS; s += 256) m = fmaxf(m, es[s]);
    red[tid] = m; __syncthreads();
    for (int st = 128; st; st >>= 1) { if (tid < st) red[tid] = fmaxf(red[tid], red[tid + st]); __syncthreads(); }
    float mx = red[0]; __syncthreads();

    float sum = 0.f;
    for (int s = tid; s < SS; s += 256) { float e = __expf(es[s] - mx); es[s] = e; sum += e; }
    red[tid] = sum; __syncthreads();
    for (int st = 128; st; st >>= 1) { if (tid < st) red[tid] += red[tid + st]; __syncthreads(); }
    float inv = 1.f / red[0]; __syncthreads();

    for (int s = tid; s < SS; s += 256) { float a = es[s] * inv; es[s] = a; ATTN[(size_t)row * SS + s] = a; }
    __syncthreads();

    float a0 = 0.f, a1 = 0.f, a2 = 0.f, a3 = 0.f;
    for (int s = 0; s < SS; s++) {
        float a = es[s];
        const float* er = ENC + ((size_t)n * SS + s) * 1024;
        a0 += a * er[tid];
        a1 += a * er[tid + 256];
        a2 += a * er[tid + 512];
        a3 += a * er[tid + 768];
    }
    CTX[(size_t)row * 1024 + tid]       = a0;
    CTX[(size_t)row * 1024 + tid + 256] = a1;
    CTX[(size_t)row * 1024 + tid + 512] = a2;
    CTX[(size_t)row * 1024 + tid + 768] = a3;
}

// ---------------- concat [h, ctx] --------------------------------------------------
__global__ void concat_kernel(const float* __restrict__ H, const float* __restrict__ CTX,
                              float* __restrict__ C)
{
    int row = blockIdx.x;
    for (int i = threadIdx.x; i < G3; i += 256)
        C[(size_t)row * G3 + i] = (i < HH) ? H[(size_t)row * HH + i]
                                           : CTX[(size_t)row * 1024 + (i - HH)];
}

// ---------------- row softmax over V (stores exp, and 1/sum) ----------------------
__global__ void softmax_kernel(float* __restrict__ LOG, float* __restrict__ invs)
{
    const int row = blockIdx.x, tid = threadIdx.x;
    float* p = LOG + (size_t)row * VV;
    __shared__ float red[256];
    float m = -1e30f;
    for (int i = tid; i < VV; i += 256) m = fmaxf(m, p[i]);
    red[tid] = m; __syncthreads();
    for (int st = 128; st; st >>= 1) { if (tid < st) red[tid] = fmaxf(red[tid], red[tid + st]); __syncthreads(); }
    float mx = red[0]; __syncthreads();
    float sum = 0.f;
    for (int i = tid; i < VV; i += 256) { float e = __expf(p[i] - mx); p[i] = e; sum += e; }
    red[tid] = sum; __syncthreads();
    for (int st = 128; st; st >>= 1) { if (tid < st) red[tid] += red[tid + st]; __syncthreads(); }
    if (tid == 0) invs[row] = 1.f / red[0];
}

// ---------------- p_gen = sigmoid([xi, ctx, h] @ Wp + bp) -------------------------
__global__ void pgen_kernel(const float* __restrict__ Xtrg, const float* __restrict__ CTX,
                            const float* __restrict__ H, const float* __restrict__ Wp,
                            const float* __restrict__ bp, float* __restrict__ pg)
{
    const int warp = threadIdx.x >> 5, lane = threadIdx.x & 31;
    const int row = blockIdx.x * 8 + warp;
    float part = 0.f;
    for (int k = lane; k < 1792; k += 32) {
        float xv;
        if (k < 256)       xv = Xtrg[(size_t)row * EE + k];
        else if (k < 1280) xv = CTX[(size_t)row * 1024 + (k - 256)];
        else               xv = H[(size_t)row * HH + (k - 1280)];
        part += xv * Wp[k];
    }
#pragma unroll
    for (int o = 16; o; o >>= 1) part += __shfl_xor_sync(0xffffffffu, part, o);
    if (lane == 0) pg[row] = fsigmoid(part + bp[0]);
}

// ---------------- out = p_gen * gen_ext (OOV region zeroed) -----------------------
__global__ void outfill_kernel(const float* __restrict__ LOG, const float* __restrict__ pg,
                               const float* __restrict__ invs, float* __restrict__ out)
{
    const int row = blockIdx.y;          // t*32 + n
    const int t = row / NB, n = row % NB;
    const int vv = blockIdx.x * 256 + threadIdx.x;
    if (vv >= VO) return;
    float val = 0.f;
    if (vv < VV) val = pg[row] * invs[row] * LOG[(size_t)row * VV + vv];
    out[((size_t)n * TDD + t) * VO + vv] = val;
}

// ---------------- deterministic scatter-add of (1-p)*attn at ptr indices ----------
__global__ void scatter_kernel(const float* __restrict__ ATTN, const float* __restrict__ pg,
                               const int* __restrict__ ptr_idx, float* __restrict__ out)
{
    const int row = blockIdx.x;          // t*32 + n
    const int t = row / NB, n = row % NB;
    __shared__ int   sidx[SS];
    __shared__ float sw[SS];
    const int s = threadIdx.x;
    const float om = 1.f - pg[row];
    if (s < SS) {
        sidx[s] = ptr_idx[n * SS + s];
        sw[s]   = om * ATTN[(size_t)row * SS + s];
    }
    __syncthreads();
    if (s < SS) {
        int my = sidx[s];
        bool first = true;
        for (int s2 = 0; s2 < s; s2++) if (sidx[s2] == my) { first = false; break; }
        if (first) {
            float val = sw[s];
            for (int s2 = s + 1; s2 < SS; s2++) if (sidx[s2] == my) val += sw[s2];
            out[((size_t)n * TDD + t) * VO + my] += val;   // rows exclusive -> no atomics
        }
    }
}

// ---------------- launch --------------------------------------------------------
extern "C" void kernel_launch(void* const* d_in, const int* in_sizes, int n_in,
                              void* d_out, int out_size)
{
    const int*   src_ids  = (const int*)  d_in[0];
    const float* src_mask = (const float*)d_in[1];
    const int*   trg_ids  = (const int*)  d_in[2];
    const int*   ptr_idx  = (const int*)  d_in[3];
    const float* embed    = (const float*)d_in[4];
    const float* Wih_f = (const float*)d_in[5],  *Whh_f = (const float*)d_in[6];
    const float* bih_f = (const float*)d_in[7],  *bhh_f = (const float*)d_in[8];
    const float* Wih_b = (const float*)d_in[9],  *Whh_b = (const float*)d_in[10];
    const float* bih_b = (const float*)d_in[11], *bhh_b = (const float*)d_in[12];
    const float* Wih_d = (const float*)d_in[13], *Whh_d = (const float*)d_in[14];
    const float* bih_d = (const float*)d_in[15], *bhh_d = (const float*)d_in[16];
    const float* Wk    = (const float*)d_in[17], *Wd    = (const float*)d_in[18];
    const float* battn = (const float*)d_in[19], *vvec  = (const float*)d_in[20];
    const float* W1    = (const float*)d_in[21], *b1    = (const float*)d_in[22];
    const float* W2    = (const float*)d_in[23], *b2    = (const float*)d_in[24];
    const float* Wp    = (const float*)d_in[25], *bp    = (const float*)d_in[26];
    float* out = (float*)d_out;

    float *Xsrc, *Xtrg, *Gf, *Gb, *Gd, *enc, *KP, *Ht, *Hdec, *Q, *ATTN, *CTX,
          *CONC, *GEN1, *LOG, *pg, *invs;
    int* ctr;
    cudaGetSymbolAddress((void**)&Xsrc, g_Xsrc);
    cudaGetSymbolAddress((void**)&Xtrg, g_Xtrg);
    cudaGetSymbolAddress((void**)&Gf,   g_Gf);
    cudaGetSymbolAddress((void**)&Gb,   g_Gb);
    cudaGetSymbolAddress((void**)&Gd,   g_Gd);
    cudaGetSymbolAddress((void**)&enc,  g_enc);
    cudaGetSymbolAddress((void**)&KP,   g_KP);
    cudaGetSymbolAddress((void**)&Ht,   g_Ht);
    cudaGetSymbolAddress((void**)&Hdec, g_Hdec);
    cudaGetSymbolAddress((void**)&Q,    g_Q);
    cudaGetSymbolAddress((void**)&ATTN, g_ATTN);
    cudaGetSymbolAddress((void**)&CTX,  g_CTX);
    cudaGetSymbolAddress((void**)&CONC, g_CONC);
    cudaGetSymbolAddress((void**)&GEN1, g_GEN1);
    cudaGetSymbolAddress((void**)&LOG,  g_LOG);
    cudaGetSymbolAddress((void**)&pg,   g_pg);
    cudaGetSymbolAddress((void**)&invs, g_inv);
    cudaGetSymbolAddress((void**)&ctr,  g_ctr);

    // gru: AF 16*8*32*4 u32 (64KB) + rs 16*32*33 f32 (66KB)
    const int persistSmem = (16 * 8 * 32 * 4) * 4 + (16 * 32 * 33) * 4;
    cudaFuncSetAttribute(gru_persist, cudaFuncAttributeMaxDynamicSharedMemorySize, persistSmem);
    // gemm: 3 stages x 5120 floats
    const int gemmSmem = 3 * 5120 * 4;
    cudaFuncSetAttribute(gemm_tf32, cudaFuncAttributeMaxDynamicSharedMemorySize, gemmSmem);

    // 1) embedding gathers
    gather_kernel<<<SS * NB, 256>>>(src_ids, embed, Xsrc, SS);
    gather_kernel<<<TDD * NB, 256>>>(trg_ids, embed, Xtrg, TDD);

    // 2) hoisted input projections (gmode=1: write [s][col][n] layout)
    gemm_tf32<<<dim3(CDIV(SS * NB, 128),  CDIV(G3, 128)), 256, gemmSmem>>>(Xsrc, Wih_f, bih_f, Gf, SS * NB,  G3, EE, 1, 1);
    gemm_tf32<<<dim3(CDIV(SS * NB, 128),  CDIV(G3, 128)), 256, gemmSmem>>>(Xsrc, Wih_b, bih_b, Gb, SS * NB,  G3, EE, 1, 1);
    gemm_tf32<<<dim3(CDIV(TDD * NB, 128), CDIV(G3, 128)), 256, gemmSmem>>>(Xtrg, Wih_d, bih_d, Gd, TDD * NB, G3, EE, 1, 1);

    // 3) bidirectional encoder recurrence: ONE persistent launch (per-dir barriers)
    cudaMemsetAsync(ctr, 0, 1024 * sizeof(int), 0);
    cudaMemsetAsync(Ht, 0, 2 * 2 * HH * NB * sizeof(float), 0);
    gru_persist<<<128, 512, persistSmem>>>(Gf, Gb, Whh_f, Whh_b, bhh_f, bhh_b,
                                           Ht, ctr, enc, nullptr, SS, 64, 1);

    // 4) attention keys
    gemm_tf32<<<dim3(CDIV(NB * SS, 128), CDIV(HH, 128)), 256, gemmSmem>>>(enc, Wk, nullptr, KP, NB * SS, HH, 2 * HH, 0, 0);

    // 5) decoder recurrence: ONE persistent launch (uses ctr[830..])
    cudaMemsetAsync(Ht, 0, 2 * 2 * HH * NB * sizeof(float), 0);
    gru_persist<<<64, 512, persistSmem>>>(Gd, Gd, Whh_d, Whh_d, bhh_d, bhh_d,
                                          Ht, ctr + 830, nullptr, Hdec, TDD, 64, 0);

    // 6) batched attention queries + attention + context
    gemm_tf32<<<dim3(CDIV(TDD * NB, 128), CDIV(HH, 128)), 256, gemmSmem>>>(Hdec, Wd, battn, Q, TDD * NB, HH, HH, 0, 0);
    attention_kernel<<<TDD * NB, 256>>>(Q, KP, enc, src_mask, vvec, ATTN, CTX);

    // 7) batched generator head
    concat_kernel<<<TDD * NB, 256>>>(Hdec, CTX, CONC);
    gemm_tf32<<<dim3(CDIV(TDD * NB, 128), CDIV(HH, 128)), 256, gemmSmem>>>(CONC, W1, b1, GEN1, TDD * NB, HH, G3, 0, 0);
    gemm_tf32<<<dim3(CDIV(TDD * NB, 128), CDIV(VV, 128)), 256, gemmSmem>>>(GEN1, W2, b2, LOG, TDD * NB, VV, HH, 0, 0);
    softmax_kernel<<<TDD * NB, 256>>>(LOG, invs);

    // 8) pointer mixture + output assembly
    pgen_kernel<<<(TDD * NB) / 8, 256>>>(Xtrg, CTX, Hdec, Wp, bp, pg);
    outfill_kernel<<<dim3(CDIV(VO, 256), TDD * NB), 256>>>(LOG, pg, invs, out);
    scatter_kernel<<<TDD * NB, 416>>>(ATTN, pg, ptr_idx, out);
}

// round 14
// speedup vs baseline: 4.6471x; 1.0150x over previous
#include <cuda_runtime.h>
#include <cstdint>

#define NB   32      // batch
#define SS   400     // src len
#define TDD  30      // trg len
#define EE   256     // embed
#define HH   512     // HE == HD == 512
#define G3   1536    // 3*H
#define VV   50000
#define OOVV 50
#define VO   50050

#define CDIV(a,b) (((a)+(b)-1)/(b))

// ---------------- scratch (device globals; no allocations allowed) ----------------
__device__ float g_Xsrc[SS * NB * EE];
__device__ float g_Xtrg[TDD * NB * EE];
__device__ float g_Gf[(size_t)SS * NB * G3];    // transposed: [s][col 1536][n 32]
__device__ float g_Gb[(size_t)SS * NB * G3];
__device__ float g_Gd[(size_t)TDD * NB * G3];
__device__ float g_enc[(size_t)NB * SS * 2 * HH];
__device__ float g_KP[(size_t)NB * SS * HH];
__device__ float g_Ht[2 * 2 * HH * NB];         // encoder h: [parity][dir][k/4][n][4]
__device__ float g_Ht2[2 * 2 * HH * NB];        // decoder h (separate: runs concurrently)
__device__ float g_Hdec[TDD * NB * HH];
__device__ float g_Q[TDD * NB * HH];
__device__ float g_ATTN[TDD * NB * SS];
__device__ float g_CTX[TDD * NB * 2 * HH];
__device__ float g_CONC[TDD * NB * G3];
__device__ float g_GEN1[TDD * NB * HH];
__device__ float g_LOG[(size_t)TDD * NB * VV];
__device__ float g_pg[TDD * NB];
__device__ float g_inv[TDD * NB];
__device__ int   g_ctr[1024];   // enc fwd [0..399], enc bwd [400..799], dec [830..859]

// ---------------- helpers ----------------
__device__ __forceinline__ float fsigmoid(float x) { return 1.f / (1.f + __expf(-x)); }
__device__ __forceinline__ float ftanh(float x) {           // exact-ish (GRU recurrence)
    x = fminf(fmaxf(x, -15.f), 15.f);
    float e2 = __expf(2.f * x);
    return (e2 - 1.f) / (e2 + 1.f);
}
__device__ __forceinline__ float htanh(float x) {           // HW MUFU tanh (attention only)
    float y;
    asm("tanh.approx.f32 %0, %1;" : "=f"(y) : "f"(x));
    return y;
}
__device__ __forceinline__ uint32_t f2tf(float x) {
    uint32_t u;
    asm("cvt.rna.tf32.f32 %0, %1;" : "=r"(u) : "f"(x));
    return u;
}
__device__ __forceinline__ void cpa16(uint32_t dst, const void* src, int sz) {
    asm volatile("cp.async.cg.shared.global [%0], [%1], 16, %2;"
                 :: "r"(dst), "l"(src), "r"(sz) : "memory");
}

// ---------------- embedding gather ------------------------------------------------
__global__ void gather_kernel(const int* __restrict__ ids, const float* __restrict__ embed,
                              float* __restrict__ X, int S)
{
    int row = blockIdx.x;                 // s*32 + n
    int s = row >> 5, n = row & 31;
    int id = ids[n * S + s];
    X[(size_t)row * EE + threadIdx.x] = embed[(size_t)id * EE + threadIdx.x];
}

// ---------------- tf32 tensor-core GEMM v3: cp.async 3-stage ----------------------
__global__ __launch_bounds__(256, 2) void gemm_tf32(
    const float* __restrict__ A, const float* __restrict__ B,
    const float* __restrict__ bias, float* __restrict__ C,
    int M, int N, int K, int transB, int gmode)
{
    extern __shared__ float sm[];        // 3 stages x (A 2560 + B 2560) floats
    const int bm = blockIdx.x * 128;
    const int bn = blockIdx.y * 128;
    const int tid = threadIdx.x;
    const int lane = tid & 31;
    const int warp = tid >> 5;
    const int wm = warp & 1, wn = warp >> 1;
    const uint32_t smBase = (uint32_t)__cvta_generic_to_shared(sm);

    float acc[4][4][4];
#pragma unroll
    for (int mi = 0; mi < 4; mi++)
#pragma unroll
        for (int ni = 0; ni < 4; ni++)
#pragma unroll
            for (int q = 0; q < 4; q++) acc[mi][ni][q] = 0.f;

    const int KT = K >> 4;

    auto issue = [&](int st, int k0) {   // st MUST be a stage index 0..2
        const uint32_t AsU = smBase + (uint32_t)st * 5120u * 4u;
        const uint32_t BsU = AsU + 2560u * 4u;
#pragma unroll
        for (int c = 0; c < 2; c++) {
            int idx = c * 256 + tid;
            int row = idx >> 2, cq = idx & 3;
            const float* src = A + (size_t)(bm + row) * K + k0 + cq * 4;
            int sz = (bm + row < M) ? 16 : 0;
            if (!sz) src = A;
            cpa16(AsU + (uint32_t)(row * 20 + cq * 4) * 4u, src, sz);
        }
        if (!transB) {
#pragma unroll
            for (int c = 0; c < 2; c++) {
                int idx = c * 256 + tid;
                int row = idx >> 5, cq = idx & 31;
                int col = bn + cq * 4;
                const float* src = B + (size_t)(k0 + row) * N + col;
                int rem = N - col;
                int sz = rem >= 4 ? 16 : (rem > 0 ? rem * 4 : 0);
                if (!sz) src = B;
                cpa16(BsU + (uint32_t)(row * 136 + cq * 4) * 4u, src, sz);
            }
        } else {
#pragma unroll
            for (int c = 0; c < 2; c++) {
                int idx = c * 256 + tid;
                int row = idx >> 2, cq = idx & 3;
                const float* src = B + (size_t)(bn + row) * K + k0 + cq * 4;
                int sz = (bn + row < N) ? 16 : 0;
                if (!sz) src = B;
                cpa16(BsU + (uint32_t)(row * 20 + cq * 4) * 4u, src, sz);
            }
        }
        asm volatile("cp.async.commit_group;" ::: "memory");
    };

    issue(0, 0);
    if (KT > 1) issue(1, 16);
    else asm volatile("cp.async.commit_group;" ::: "memory");

    for (int kt = 0; kt < KT; kt++) {
        const int st = kt % 3;
        asm volatile("cp.async.wait_group 1;" ::: "memory");
        __syncthreads();
        const uint32_t* As = reinterpret_cast<const uint32_t*>(sm + st * 5120);
        const uint32_t* Bs = As + 2560;
#pragma unroll
        for (int ks = 0; ks < 2; ks++) {
            uint32_t af[4][4], bf[4][2];
            const int r0 = wm * 64 + (lane >> 2);
            const int c0 = ks * 8 + (lane & 3);
#pragma unroll
            for (int mi = 0; mi < 4; mi++) {
                const int rr = r0 + mi * 16;
                af[mi][0] = As[rr * 20 + c0];
                af[mi][1] = As[(rr + 8) * 20 + c0];
                af[mi][2] = As[rr * 20 + c0 + 4];
                af[mi][3] = As[(rr + 8) * 20 + c0 + 4];
            }
#pragma unroll
            for (int ni = 0; ni < 4; ni++) {
                const int nn = wn * 32 + ni * 8 + (lane >> 2);
                if (transB) {
                    bf[ni][0] = Bs[nn * 20 + c0];
                    bf[ni][1] = Bs[nn * 20 + c0 + 4];
                } else {
                    bf[ni][0] = Bs[c0 * 136 + nn];
                    bf[ni][1] = Bs[(c0 + 4) * 136 + nn];
                }
            }
#pragma unroll
            for (int mi = 0; mi < 4; mi++)
#pragma unroll
                for (int ni = 0; ni < 4; ni++)
                    asm volatile(
                        "mma.sync.aligned.m16n8k8.row.col.f32.tf32.tf32.f32 "
                        "{%0,%1,%2,%3}, {%4,%5,%6,%7}, {%8,%9}, {%0,%1,%2,%3};"
                        : "+f"(acc[mi][ni][0]), "+f"(acc[mi][ni][1]),
                          "+f"(acc[mi][ni][2]), "+f"(acc[mi][ni][3])
                        : "r"(af[mi][0]), "r"(af[mi][1]), "r"(af[mi][2]), "r"(af[mi][3]),
                          "r"(bf[ni][0]), "r"(bf[ni][1]));
        }
        if (kt + 2 < KT) issue((kt + 2) % 3, (kt + 2) << 4);
        else asm volatile("cp.async.commit_group;" ::: "memory");
    }

#pragma unroll
    for (int mi = 0; mi < 4; mi++) {
#pragma unroll
        for (int ni = 0; ni < 4; ni++) {
            const int row = bm + wm * 64 + mi * 16 + (lane >> 2);
            const int col = bn + wn * 32 + ni * 8 + (lane & 3) * 2;
#pragma unroll
            for (int h = 0; h < 2; h++) {
                const int m = row + h * 8;
                if (m < M) {
#pragma unroll
                    for (int q = 0; q < 2; q++) {
                        const int n = col + q;
                        if (n < N) {
                            float v = acc[mi][ni][h * 2 + q];
                            if (bias) v += __ldg(&bias[n]);
                            if (gmode) C[((size_t)(m >> 5) * N + n) * 32 + (m & 31)] = v;
                            else       C[(size_t)m * N + n] = v;
                        }
                    }
                }
            }
        }
    }
}

// ---------------- persistent GRU recurrence (tensor-core, 512 threads) ------------
__global__ __launch_bounds__(512, 1) void gru_persist(
    const float* __restrict__ G0T, const float* __restrict__ G1T,
    const float* __restrict__ Whh0, const float* __restrict__ Whh1,
    const float* __restrict__ bhh0, const float* __restrict__ bhh1,
    float* __restrict__ Ht, int* ctr,
    float* __restrict__ encOut, float* __restrict__ hdecOut,
    int nSteps, int nCTA, int encMode)
{
    extern __shared__ uint32_t smemU[];
    uint32_t* AF = smemU;                              // [16 warps][8 (mi*4+ki)][32 lanes][4]
    float* rs = reinterpret_cast<float*>(smemU + 16 * 8 * 32 * 4);  // [16*32 rows][33]

    const int dir   = encMode ? (blockIdx.x >> 6) : 0;
    const int utile = blockIdx.x & 63;
    const int u0 = utile * 8;
    const float* Whh = dir ? Whh1 : Whh0;
    const float* bhh = dir ? bhh1 : bhh0;
    const float* GT  = dir ? G1T  : G0T;

    const int tid = threadIdx.x, lane = tid & 31, wk = tid >> 5;   // wk 0..15

#pragma unroll
    for (int mi = 0; mi < 2; mi++)
#pragma unroll
        for (int ki = 0; ki < 4; ki++)
#pragma unroll
            for (int r = 0; r < 4; r++) {
                int row = mi * 16 + (lane >> 2) + (r & 1) * 8;           // gate-row c
                int col = wk * 32 + ki * 8 + (lane & 3) + (r >> 1) * 4;  // k
                float v = 0.f;
                if (row < 24)
                    v = Whh[((size_t)((row >> 3) * 512 + u0 + (row & 7))) * 512 + col];
                AF[((wk * 8 + mi * 4 + ki) * 32 + lane) * 4 + r] = f2tf(v);
            }
    float b_r = 0.f, b_z = 0.f, b_n = 0.f;
    const int u = u0 + wk;               // valid for wk < 8
    if (wk < 8) {
        b_r = bhh[u];
        b_z = bhh[512 + u];
        b_n = bhh[1024 + u];
    }
    __syncthreads();

    float hprev = 0.f;

    for (int t = 0; t < nSteps; t++) {
        const int p = t & 1;
        const float* Hp = Ht + ((size_t)p * 2 + dir) * HH * NB;
        float*       Hn = Ht + ((size_t)(1 - p) * 2 + dir) * HH * NB;
        const int gidx = dir ? (nSteps - 1 - t) : t;
        const float* Gt = GT + (size_t)gidx * G3 * NB;

        float gir = 0.f, giz = 0.f, gin = 0.f;
        if (wk < 8) {
            gir = __ldg(&Gt[u * 32 + lane]);
            giz = __ldg(&Gt[(512 + u) * 32 + lane]);
            gin = __ldg(&Gt[(1024 + u) * 32 + lane]);
        }

        uint32_t bReg[4][4][2];          // [ni][ki][2]
        const int kq = wk * 8;
#pragma unroll
        for (int ki = 0; ki < 4; ki++)
#pragma unroll
            for (int ni = 0; ni < 4; ni++) {
                float v0 = __ldcg(&Hp[(kq + ki * 2) * 128 + ni * 32 + lane]);
                float v1 = __ldcg(&Hp[(kq + ki * 2 + 1) * 128 + ni * 32 + lane]);
                bReg[ni][ki][0] = f2tf(v0);
                bReg[ni][ki][1] = f2tf(v1);
            }

        float acc[2][4][4];
#pragma unroll
        for (int mi = 0; mi < 2; mi++)
#pragma unroll
            for (int ni = 0; ni < 4; ni++)
#pragma unroll
                for (int q = 0; q < 4; q++) acc[mi][ni][q] = 0.f;

#pragma unroll
        for (int mi = 0; mi < 2; mi++)
#pragma unroll
            for (int ki = 0; ki < 4; ki++) {
                uint4 a = *reinterpret_cast<const uint4*>(
                    &AF[((wk * 8 + mi * 4 + ki) * 32 + lane) * 4]);
#pragma unroll
                for (int ni = 0; ni < 4; ni++)
                    asm volatile(
                        "mma.sync.aligned.m16n8k8.row.col.f32.tf32.tf32.f32 "
                        "{%0,%1,%2,%3}, {%4,%5,%6,%7}, {%8,%9}, {%0,%1,%2,%3};"
                        : "+f"(acc[mi][ni][0]), "+f"(acc[mi][ni][1]),
                          "+f"(acc[mi][ni][2]), "+f"(acc[mi][ni][3])
                        : "r"(a.x), "r"(a.y), "r"(a.z), "r"(a.w),
                          "r"(bReg[ni][ki][0]), "r"(bReg[ni][ki][1]));
            }

        {
            const int row0 = lane >> 2, col0 = 2 * (lane & 3);
#pragma unroll
            for (int mi = 0; mi < 2; mi++)
#pragma unroll
                for (int ni = 0; ni < 4; ni++) {
                    float* base = &rs[(wk * 32 + mi * 16 + row0) * 33 + ni * 8 + col0];
                    base[0]          = acc[mi][ni][0];
                    base[1]          = acc[mi][ni][1];
                    base[33 * 8]     = acc[mi][ni][2];
                    base[33 * 8 + 1] = acc[mi][ni][3];
                }
        }
        __syncthreads();

        if (wk < 8) {
            float ar = 0.f, az = 0.f, an = 0.f;
#pragma unroll
            for (int w2 = 0; w2 < 16; w2++) {
                ar += rs[(w2 * 32 + wk) * 33 + lane];
                az += rs[(w2 * 32 + 8 + wk) * 33 + lane];
                an += rs[(w2 * 32 + 16 + wk) * 33 + lane];
            }
            float r = fsigmoid(gir + ar + b_r);
            float z = fsigmoid(giz + az + b_z);
            float nn = ftanh(gin + (an + b_n) * r);
            float hnew = (1.f - z) * nn + z * hprev;
            hprev = hnew;
            __stcg(&Hn[(u >> 2) * 128 + lane * 4 + (u & 3)], hnew);
            if (encMode) {
                int s = dir ? (nSteps - 1 - t) : t;
                encOut[(size_t)lane * SS * 1024 + (size_t)s * 1024 + dir * 512 + u] = hnew;
            } else {
                hdecOut[(size_t)t * NB * HH + (size_t)lane * HH + u] = hnew;
            }
        }
        __syncthreads();

        if (t + 1 < nSteps) {
            if (tid == 0) {
                int* a = &ctr[dir ? (nSteps + t) : t];
                asm volatile("red.release.gpu.global.add.u32 [%0], 1;" :: "l"(a) : "memory");
                unsigned v;
                do {
                    asm volatile("ld.acquire.gpu.global.u32 %0, [%1];" : "=r"(v) : "l"(a) : "memory");
                } while (v < (unsigned)nCTA);
            }
            __syncthreads();
        }
    }
}

// ---------------- attention scores + softmax (one CTA per (t,n) row) --------------
__global__ void score_kernel(const float* __restrict__ Q, const float* __restrict__ KP,
                             const float* __restrict__ mask, const float* __restrict__ vvec,
                             float* __restrict__ ATTN)
{
    const int row = blockIdx.x;          // t*32 + n
    const int n = row & 31;
    const int tid = threadIdx.x, lane = tid & 31, warp = tid >> 5;
    __shared__ float qs[HH], vs[HH], es[SS], red[256];

    for (int i = tid; i < HH; i += 256) { qs[i] = Q[(size_t)row * HH + i]; vs[i] = vvec[i]; }
    __syncthreads();

    for (int s = warp; s < SS; s += 8) {
        const float* kp = KP + ((size_t)n * SS + s) * HH;
        float part = 0.f;
        for (int d = lane; d < HH; d += 32)
            part += htanh(kp[d] + qs[d]) * vs[d];
#pragma unroll
        for (int o = 16; o; o >>= 1) part += __shfl_xor_sync(0xffffffffu, part, o);
        if (lane == 0) es[s] = part + (1.f - mask[n * SS + s]) * (-1e10f);
    }
    __syncthreads();

    float m = -1e30f;
    for (int s = tid; s < SS; s += 256) m = fmaxf(m, es[s]);
    red[tid] = m; __syncthreads();
    for (int st = 128; st; st >>= 1) { if (tid < st) red[tid] = fmaxf(red[tid], red[tid + st]); __syncthreads(); }
    float mx = red[0]; __syncthreads();

    float sum = 0.f;
    for (int s = tid; s < SS; s += 256) { float e = __expf(es[s] - mx); es[s] = e; sum += e; }
    red[tid] = sum; __syncthreads();
    for (int st = 128; st; st >>= 1) { if (tid < st) red[tid] += red[tid + st]; __syncthreads(); }
    float inv = 1.f / red[0]; __syncthreads();

    for (int s = tid; s < SS; s += 256)
        ATTN[(size_t)row * SS + s] = es[s] * inv;
}

// ---------------- context: CTX[t,n,:] = sum_s ATTN[t,n,s] * enc[n,s,:] ------------
// grid (4 dchunks, 32 n), 256 threads; enc read ONCE; acc[30] in registers.
__global__ __launch_bounds__(256) void ctx_kernel(
    const float* __restrict__ ATTN, const float* __restrict__ ENC,
    float* __restrict__ CTX)
{
    const int n = blockIdx.y;
    const int d = blockIdx.x * 256 + threadIdx.x;
    const int tid = threadIdx.x;
    __shared__ float at[TDD][129];

    float acc[TDD];
#pragma unroll
    for (int t = 0; t < TDD; t++) acc[t] = 0.f;

    for (int s0 = 0; s0 < SS; s0 += 128) {
        __syncthreads();
        for (int idx = tid; idx < TDD * 128; idx += 256) {
            int t = idx >> 7, si = idx & 127;
            at[t][si] = (s0 + si < SS) ? ATTN[((size_t)(t * NB + n)) * SS + s0 + si] : 0.f;
        }
        __syncthreads();
        const int lim = min(128, SS - s0);
        for (int si = 0; si < lim; si++) {
            float e = __ldg(&ENC[((size_t)n * SS + s0 + si) * 1024 + d]);
#pragma unroll
            for (int t = 0; t < TDD; t++) acc[t] = fmaf(at[t][si], e, acc[t]);
        }
    }
#pragma unroll
    for (int t = 0; t < TDD; t++)
        CTX[((size_t)(t * NB + n)) * 1024 + d] = acc[t];
}

// ---------------- concat [h, ctx] --------------------------------------------------
__global__ void concat_kernel(const float* __restrict__ H, const float* __restrict__ CTX,
                              float* __restrict__ C)
{
    int row = blockIdx.x;
    for (int i = threadIdx.x; i < G3; i += 256)
        C[(size_t)row * G3 + i] = (i < HH) ? H[(size_t)row * HH + i]
                                           : CTX[(size_t)row * 1024 + (i - HH)];
}

// ---------------- row softmax over V (stores exp, and 1/sum) ----------------------
__global__ void softmax_kernel(float* __restrict__ LOG, float* __restrict__ invs)
{
    const int row = blockIdx.x, tid = threadIdx.x;
    float* p = LOG + (size_t)row * VV;
    __shared__ float red[256];
    float m = -1e30f;
    for (int i = tid; i < VV; i += 256) m = fmaxf(m, p[i]);
    red[tid] = m; __syncthreads();
    for (int st = 128; st; st >>= 1) { if (tid < st) red[tid] = fmaxf(red[tid], red[tid + st]); __syncthreads(); }
    float mx = red[0]; __syncthreads();
    float sum = 0.f;
    for (int i = tid; i < VV; i += 256) { float e = __expf(p[i] - mx); p[i] = e; sum += e; }
    red[tid] = sum; __syncthreads();
    for (int st = 128; st; st >>= 1) { if (tid < st) red[tid] += red[tid + st]; __syncthreads(); }
    if (tid == 0) invs[row] = 1.f / red[0];
}

// ---------------- p_gen = sigmoid([xi, ctx, h] @ Wp + bp) -------------------------
__global__ void pgen_kernel(const float* __restrict__ Xtrg, const float* __restrict__ CTX,
                            const float* __restrict__ H, const float* __restrict__ Wp,
                            const float* __restrict__ bp, float* __restrict__ pg)
{
    const int warp = threadIdx.x >> 5, lane = threadIdx.x & 31;
    const int row = blockIdx.x * 8 + warp;
    float part = 0.f;
    for (int k = lane; k < 1792; k += 32) {
        float xv;
        if (k < 256)       xv = Xtrg[(size_t)row * EE + k];
        else if (k < 1280) xv = CTX[(size_t)row * 1024 + (k - 256)];
        else               xv = H[(size_t)row * HH + (k - 1280)];
        part += xv * Wp[k];
    }
#pragma unroll
    for (int o = 16; o; o >>= 1) part += __shfl_xor_sync(0xffffffffu, part, o);
    if (lane == 0) pg[row] = fsigmoid(part + bp[0]);
}

// ---------------- out = p_gen * gen_ext (OOV region zeroed) -----------------------
__global__ void outfill_kernel(const float* __restrict__ LOG, const float* __restrict__ pg,
                               const float* __restrict__ invs, float* __restrict__ out)
{
    const int row = blockIdx.y;          // t*32 + n
    const int t = row / NB, n = row % NB;
    const int vv = blockIdx.x * 256 + threadIdx.x;
    if (vv >= VO) return;
    float val = 0.f;
    if (vv < VV) val = pg[row] * invs[row] * LOG[(size_t)row * VV + vv];
    out[((size_t)n * TDD + t) * VO + vv] = val;
}

// ---------------- deterministic scatter-add of (1-p)*attn at ptr indices ----------
__global__ void scatter_kernel(const float* __restrict__ ATTN, const float* __restrict__ pg,
                               const int* __restrict__ ptr_idx, float* __restrict__ out)
{
    const int row = blockIdx.x;          // t*32 + n
    const int t = row / NB, n = row % NB;
    __shared__ int   sidx[SS];
    __shared__ float sw[SS];
    const int s = threadIdx.x;
    const float om = 1.f - pg[row];
    if (s < SS) {
        sidx[s] = ptr_idx[n * SS + s];
        sw[s]   = om * ATTN[(size_t)row * SS + s];
    }
    __syncthreads();
    if (s < SS) {
        int my = sidx[s];
        bool first = true;
        for (int s2 = 0; s2 < s; s2++) if (sidx[s2] == my) { first = false; break; }
        if (first) {
            float val = sw[s];
            for (int s2 = s + 1; s2 < SS; s2++) if (sidx[s2] == my) val += sw[s2];
            out[((size_t)n * TDD + t) * VO + my] += val;   // rows exclusive -> no atomics
        }
    }
}

// ---------------- launch --------------------------------------------------------
extern "C" void kernel_launch(void* const* d_in, const int* in_sizes, int n_in,
                              void* d_out, int out_size)
{
    const int*   src_ids  = (const int*)  d_in[0];
    const float* src_mask = (const float*)d_in[1];
    const int*   trg_ids  = (const int*)  d_in[2];
    const int*   ptr_idx  = (const int*)  d_in[3];
    const float* embed    = (const float*)d_in[4];
    const float* Wih_f = (const float*)d_in[5],  *Whh_f = (const float*)d_in[6];
    const float* bih_f = (const float*)d_in[7],  *bhh_f = (const float*)d_in[8];
    const float* Wih_b = (const float*)d_in[9],  *Whh_b = (const float*)d_in[10];
    const float* bih_b = (const float*)d_in[11], *bhh_b = (const float*)d_in[12];
    const float* Wih_d = (const float*)d_in[13], *Whh_d = (const float*)d_in[14];
    const float* bih_d = (const float*)d_in[15], *bhh_d = (const float*)d_in[16];
    const float* Wk    = (const float*)d_in[17], *Wd    = (const float*)d_in[18];
    const float* battn = (const float*)d_in[19], *vvec  = (const float*)d_in[20];
    const float* W1    = (const float*)d_in[21], *b1    = (const float*)d_in[22];
    const float* W2    = (const float*)d_in[23], *b2    = (const float*)d_in[24];
    const float* Wp    = (const float*)d_in[25], *bp    = (const float*)d_in[26];
    float* out = (float*)d_out;

    float *Xsrc, *Xtrg, *Gf, *Gb, *Gd, *enc, *KP, *Ht, *Ht2, *Hdec, *Q, *ATTN, *CTX,
          *CONC, *GEN1, *LOG, *pg, *invs;
    int* ctr;
    cudaGetSymbolAddress((void**)&Xsrc, g_Xsrc);
    cudaGetSymbolAddress((void**)&Xtrg, g_Xtrg);
    cudaGetSymbolAddress((void**)&Gf,   g_Gf);
    cudaGetSymbolAddress((void**)&Gb,   g_Gb);
    cudaGetSymbolAddress((void**)&Gd,   g_Gd);
    cudaGetSymbolAddress((void**)&enc,  g_enc);
    cudaGetSymbolAddress((void**)&KP,   g_KP);
    cudaGetSymbolAddress((void**)&Ht,   g_Ht);
    cudaGetSymbolAddress((void**)&Ht2,  g_Ht2);
    cudaGetSymbolAddress((void**)&Hdec, g_Hdec);
    cudaGetSymbolAddress((void**)&Q,    g_Q);
    cudaGetSymbolAddress((void**)&ATTN, g_ATTN);
    cudaGetSymbolAddress((void**)&CTX,  g_CTX);
    cudaGetSymbolAddress((void**)&CONC, g_CONC);
    cudaGetSymbolAddress((void**)&GEN1, g_GEN1);
    cudaGetSymbolAddress((void**)&LOG,  g_LOG);
    cudaGetSymbolAddress((void**)&pg,   g_pg);
    cudaGetSymbolAddress((void**)&invs, g_inv);
    cudaGetSymbolAddress((void**)&ctr,  g_ctr);

    const int persistSmem = (16 * 8 * 32 * 4) * 4 + (16 * 32 * 33) * 4;
    cudaFuncSetAttribute(gru_persist, cudaFuncAttributeMaxDynamicSharedMemorySize, persistSmem);
    const int gemmSmem = 3 * 5120 * 4;
    cudaFuncSetAttribute(gemm_tf32, cudaFuncAttributeMaxDynamicSharedMemorySize, gemmSmem);

    // Fork a side stream for the (independent) decoder chain. Created per call,
    // deliberately not destroyed (kernel_launch runs only twice; replays use the graph).
    cudaStream_t s2;
    cudaStreamCreateWithFlags(&s2, cudaStreamNonBlocking);
    cudaEvent_t evF, evJ;
    cudaEventCreateWithFlags(&evF, cudaEventDisableTiming);
    cudaEventCreateWithFlags(&evJ, cudaEventDisableTiming);

    cudaEventRecord(evF, 0);
    cudaStreamWaitEvent(s2, evF, 0);

    // ---- side stream: Xtrg gather -> Gd proj -> decoder recurrence -> Q proj ----
    gather_kernel<<<TDD * NB, 256, 0, s2>>>(trg_ids, embed, Xtrg, TDD);
    cudaMemsetAsync(ctr + 830, 0, 64 * sizeof(int), s2);
    cudaMemsetAsync(Ht2, 0, 2 * 2 * HH * NB * sizeof(float), s2);
    gemm_tf32<<<dim3(CDIV(TDD * NB, 128), CDIV(G3, 128)), 256, gemmSmem, s2>>>(
        Xtrg, Wih_d, bih_d, Gd, TDD * NB, G3, EE, 1, 1);
    gru_persist<<<64, 512, persistSmem, s2>>>(Gd, Gd, Whh_d, Whh_d, bhh_d, bhh_d,
                                              Ht2, ctr + 830, nullptr, Hdec, TDD, 64, 0);
    gemm_tf32<<<dim3(CDIV(TDD * NB, 128), CDIV(HH, 128)), 256, gemmSmem, s2>>>(
        Hdec, Wd, battn, Q, TDD * NB, HH, HH, 0, 0);
    cudaEventRecord(evJ, s2);

    // ---- main stream: encoder chain ----
    gather_kernel<<<SS * NB, 256>>>(src_ids, embed, Xsrc, SS);
    gemm_tf32<<<dim3(CDIV(SS * NB, 128), CDIV(G3, 128)), 256, gemmSmem>>>(
        Xsrc, Wih_f, bih_f, Gf, SS * NB, G3, EE, 1, 1);
    gemm_tf32<<<dim3(CDIV(SS * NB, 128), CDIV(G3, 128)), 256, gemmSmem>>>(
        Xsrc, Wih_b, bih_b, Gb, SS * NB, G3, EE, 1, 1);
    cudaMemsetAsync(ctr, 0, 800 * sizeof(int), 0);
    cudaMemsetAsync(Ht, 0, 2 * 2 * HH * NB * sizeof(float), 0);
    gru_persist<<<128, 512, persistSmem>>>(Gf, Gb, Whh_f, Whh_b, bhh_f, bhh_b,
                                           Ht, ctr, enc, nullptr, SS, 64, 1);
    gemm_tf32<<<dim3(CDIV(NB * SS, 128), CDIV(HH, 128)), 256, gemmSmem>>>(
        enc, Wk, nullptr, KP, NB * SS, HH, 2 * HH, 0, 0);

    // ---- join, then attention + generator head ----
    cudaStreamWaitEvent(0, evJ, 0);
    score_kernel<<<TDD * NB, 256>>>(Q, KP, src_mask, vvec, ATTN);
    ctx_kernel<<<dim3(4, NB), 256>>>(ATTN, enc, CTX);

    concat_kernel<<<TDD * NB, 256>>>(Hdec, CTX, CONC);
    gemm_tf32<<<dim3(CDIV(TDD * NB, 128), CDIV(HH, 128)), 256, gemmSmem>>>(
        CONC, W1, b1, GEN1, TDD * NB, HH, G3, 0, 0);
    gemm_tf32<<<dim3(CDIV(TDD * NB, 128), CDIV(VV, 128)), 256, gemmSmem>>>(
        GEN1, W2, b2, LOG, TDD * NB, VV, HH, 0, 0);
    softmax_kernel<<<TDD * NB, 256>>>(LOG, invs);

    pgen_kernel<<<(TDD * NB) / 8, 256>>>(Xtrg, CTX, Hdec, Wp, bp, pg);
    outfill_kernel<<<dim3(CDIV(VO, 256), TDD * NB), 256>>>(LOG, pg, invs, out);
    scatter_kernel<<<TDD * NB, 416>>>(ATTN, pg, ptr_idx, out);
}